// round 1
// baseline (speedup 1.0000x reference)
#include <cuda_runtime.h>
#include <cuda_bf16.h>

// Problem constants (fixed shapes per reference setup_inputs)
#define BSZ 4
#define CCH 256
#define HH 64
#define WW 64
#define HWN (HH*WW)          // 4096
#define GG 4
#define CG (CCH/GG)          // 64
#define PP 9

// ---------------- scratch (device globals; no allocation allowed) ----------------
__device__ float g_x2d[BSZ * CCH * HWN];   // x transposed to [B,C,H,W]
__device__ float g_h  [BSZ * CCH * HWN];   // offset branch hidden
__device__ float g_off[BSZ * (GG*2*PP) * HWN];  // 72 channels
__device__ float g_m  [BSZ * (CCH/4) * HWN];    // 64 channels
__device__ float g_mod[BSZ * (GG*PP) * HWN];    // 36 channels

// ---------------- transpose: [B, HW, C] -> [B, C, HW] ----------------
__global__ void transpose_kernel(const float* __restrict__ x, float* __restrict__ x2d) {
    __shared__ float tile[32][33];
    int b  = blockIdx.z;
    int n0 = blockIdx.x * 32;   // HW dim
    int c0 = blockIdx.y * 32;   // C dim
    int tx = threadIdx.x, ty = threadIdx.y; // 32 x 8
    #pragma unroll
    for (int i = ty; i < 32; i += 8)
        tile[i][tx] = x[((size_t)b*HWN + n0 + i)*CCH + c0 + tx];
    __syncthreads();
    #pragma unroll
    for (int i = ty; i < 32; i += 8)
        x2d[((size_t)b*CCH + c0 + i)*HWN + n0 + tx] = tile[tx][i];
}

// ---------------- direct 3x3 SAME conv, NCHW, optional groups ----------------
// Block: 256 threads = 16x16 spatial tile. Each thread owns COUT_TILE accumulators.
// Input channels processed 4 at a time (float4 smem), weights as float4 per k.
// act: 0 = none, 1 = exact GELU, 2 = sigmoid
template<int COUT_TILE>
__global__ void __launch_bounds__(256) conv3x3_kernel(
    const float* __restrict__ in,    // [B, Cin, 64, 64]
    const float* __restrict__ wgt,   // [Cout, cinG, 3, 3]
    const float* __restrict__ bias,  // [Cout]
    float* __restrict__ out,         // [B, Cout, 64, 64]
    int Cin, int Cout, int cinG, int coutG, int act)
{
    const int tx = threadIdx.x & 15;
    const int ty = threadIdx.x >> 4;
    const int tileX = blockIdx.x * 16;
    const int b     = blockIdx.y >> 2;
    const int tileY = (blockIdx.y & 3) * 16;
    const int co0   = blockIdx.z * COUT_TILE;
    const int grp   = co0 / coutG;
    const int ciBase = grp * cinG;

    __shared__ float4 sIn[18*18];
    __shared__ float4 sW [COUT_TILE*9];

    float acc[COUT_TILE];
    #pragma unroll
    for (int i = 0; i < COUT_TILE; i++) acc[i] = 0.f;

    for (int ci = 0; ci < cinG; ci += 4) {
        // cooperative input tile load (18x18, 4 channels interleaved)
        const float* ip = in + (((size_t)b*Cin + ciBase + ci)*HH)*WW;
        for (int i = threadIdx.x; i < 18*18; i += 256) {
            int yy = i / 18, xx = i % 18;
            int gy = tileY + yy - 1, gx = tileX + xx - 1;
            float4 v = make_float4(0.f,0.f,0.f,0.f);
            if (gy >= 0 && gy < HH && gx >= 0 && gx < WW) {
                const float* p = ip + gy*WW + gx;
                v.x = p[0];
                v.y = p[HWN];
                v.z = p[2*HWN];
                v.w = p[3*HWN];
            }
            sIn[i] = v;
        }
        // weight load: COUT_TILE*9 float4
        if (threadIdx.x < COUT_TILE*9) {
            int co = threadIdx.x / 9, k = threadIdx.x % 9;
            const float* wp = wgt + ((size_t)(co0+co)*cinG + ci)*9 + k;
            sW[threadIdx.x] = make_float4(wp[0], wp[9], wp[18], wp[27]);
        }
        __syncthreads();

        float4 r[9];
        #pragma unroll
        for (int dy = 0; dy < 3; dy++)
            #pragma unroll
            for (int dx = 0; dx < 3; dx++)
                r[dy*3+dx] = sIn[(ty+dy)*18 + tx + dx];

        #pragma unroll
        for (int co = 0; co < COUT_TILE; co++) {
            float a = acc[co];
            #pragma unroll
            for (int k = 0; k < 9; k++) {
                float4 w = sW[co*9 + k];
                a += r[k].x*w.x;
                a += r[k].y*w.y;
                a += r[k].z*w.z;
                a += r[k].w*w.w;
            }
            acc[co] = a;
        }
        __syncthreads();
    }

    const int oy = tileY + ty, ox = tileX + tx;
    #pragma unroll
    for (int co = 0; co < COUT_TILE; co++) {
        float v = acc[co] + bias[co0 + co];
        if (act == 1)      v = v * normcdff(v);                 // exact GELU
        else if (act == 2) v = 1.f / (1.f + expf(-v));          // sigmoid
        out[(((size_t)b*Cout + co0 + co)*HH + oy)*WW + ox] = v;
    }
}

// ---------------- deformable bilinear sampling + modulation + mean over P ----------------
// x kept in native [B, HW, C] layout -> channel-contiguous gathers (coalesced).
// Block: 256 threads = 4 pixels x 64 channels (one group).
__global__ void __launch_bounds__(256) sample_kernel(
    const float* __restrict__ x,    // [B, HW, C]
    const float* __restrict__ off,  // [B, 72, HW]  (g*18 + d*9 + p)
    const float* __restrict__ mod,  // [B, 36, HW]  (g*9 + p), post-sigmoid
    float* __restrict__ out)        // [B, HW, C]
{
    const int t   = threadIdx.x;
    const int c   = t & 63;          // channel within group
    const int pl  = t >> 6;          // local pixel 0..3
    const int pix = blockIdx.x * 4 + pl;
    const int g   = blockIdx.y;
    const int b   = blockIdx.z;
    const int yq  = pix >> 6;
    const int xq  = pix & 63;

    const float* offp = off + ((size_t)b*72 + g*18)*HWN + pix;
    const float* modp = mod + ((size_t)b*36 + g*9 )*HWN + pix;
    const float* xb   = x   + (size_t)b*HWN*CCH + g*CG + c;

    float acc = 0.f;
    #pragma unroll
    for (int p = 0; p < 9; p++) {
        float ox = offp[(size_t)p*HWN];
        float oy = offp[(size_t)(9+p)*HWN];
        float mv = modp[(size_t)p*HWN];

        float px = fminf(fmaxf((float)(xq + (p%3) - 1) + ox, 0.f), (float)(WW-1));
        float py = fminf(fmaxf((float)(yq + (p/3) - 1) + oy, 0.f), (float)(HH-1));

        float x0f = floorf(px), y0f = floorf(py);
        float wx = px - x0f, wy = py - y0f;
        int x0 = (int)x0f, y0 = (int)y0f;
        int x1 = min(x0 + 1, WW-1);
        int y1 = min(y0 + 1, HH-1);

        float v00 = xb[(size_t)(y0*WW + x0)*CCH];
        float v01 = xb[(size_t)(y0*WW + x1)*CCH];
        float v10 = xb[(size_t)(y1*WW + x0)*CCH];
        float v11 = xb[(size_t)(y1*WW + x1)*CCH];

        float top = v00 + wx*(v01 - v00);
        float bot = v10 + wx*(v11 - v10);
        acc += (top + wy*(bot - top)) * mv;
    }
    out[((size_t)b*HWN + pix)*CCH + g*CG + c] = acc * (1.f/9.f);
}

// ---------------- launch ----------------
extern "C" void kernel_launch(void* const* d_in, const int* in_sizes, int n_in,
                              void* d_out, int out_size)
{
    const float* x      = (const float*)d_in[0];
    const float* off_w1 = (const float*)d_in[1];
    const float* off_b1 = (const float*)d_in[2];
    const float* off_w2 = (const float*)d_in[3];
    const float* off_b2 = (const float*)d_in[4];
    const float* mod_w1 = (const float*)d_in[5];
    const float* mod_b1 = (const float*)d_in[6];
    const float* mod_w2 = (const float*)d_in[7];
    const float* mod_b2 = (const float*)d_in[8];
    float* out = (float*)d_out;

    float* x2d; cudaGetSymbolAddress((void**)&x2d, g_x2d);
    float* h;   cudaGetSymbolAddress((void**)&h,   g_h);
    float* off; cudaGetSymbolAddress((void**)&off, g_off);
    float* m;   cudaGetSymbolAddress((void**)&m,   g_m);
    float* md;  cudaGetSymbolAddress((void**)&md,  g_mod);

    // 1) transpose x -> x2d [B,C,H,W]
    {
        dim3 grid(HWN/32, CCH/32, BSZ), blk(32, 8);
        transpose_kernel<<<grid, blk>>>(x, x2d);
    }
    // 2) offset branch conv1 (grouped, G=4, cinG=64) + GELU
    {
        dim3 grid(4, 4*BSZ, 256/16);
        conv3x3_kernel<16><<<grid, 256>>>(x2d, off_w1, off_b1, h, 256, 256, 64, 64, 1);
    }
    // 3) offset branch conv2 (72 <- 256), no activation
    {
        dim3 grid(4, 4*BSZ, 72/12);
        conv3x3_kernel<12><<<grid, 256>>>(h, off_w2, off_b2, off, 256, 72, 256, 72, 0);
    }
    // 4) modulation branch conv1 (64 <- 256) + GELU
    {
        dim3 grid(4, 4*BSZ, 64/16);
        conv3x3_kernel<16><<<grid, 256>>>(x2d, mod_w1, mod_b1, m, 256, 64, 256, 64, 1);
    }
    // 5) modulation branch conv2 (36 <- 64) + sigmoid
    {
        dim3 grid(4, 4*BSZ, 36/12);
        conv3x3_kernel<12><<<grid, 256>>>(m, mod_w2, mod_b2, md, 64, 36, 64, 36, 2);
    }
    // 6) deformable sampling from native-layout x
    {
        dim3 grid(HWN/4, GG, BSZ);
        sample_kernel<<<grid, 256>>>(x, off, md, out);
    }
}

// round 2
// speedup vs baseline: 1.3217x; 1.3217x over previous
#include <cuda_runtime.h>
#include <cuda_bf16.h>

#define BSZ 4
#define CCH 256
#define HH 64
#define WW 64
#define HWN (HH*WW)          // 4096
#define GG 4
#define CG (CCH/GG)          // 64

// ---------------- scratch ----------------
__device__ float g_x2d [BSZ * CCH * HWN];       // x transposed [B,C,H,W]
__device__ float g_h   [BSZ * CCH * HWN];       // off-branch hidden
__device__ float g_off [BSZ * 72 * HWN];        // off2 partial (cin 0..127, incl bias)
__device__ float g_off2[BSZ * 72 * HWN];        // off2 partial (cin 128..255)
__device__ float g_m   [BSZ * 64 * HWN];        // mod-branch hidden
__device__ float g_mod [BSZ * 36 * HWN];        // mod (post-sigmoid)

// ---------------- transpose [B,HW,C] -> [B,C,HW] ----------------
__global__ void transpose_kernel(const float* __restrict__ x, float* __restrict__ x2d) {
    __shared__ float tile[32][33];
    int b  = blockIdx.z;
    int n0 = blockIdx.x * 32;
    int c0 = blockIdx.y * 32;
    int tx = threadIdx.x, ty = threadIdx.y; // 32 x 8
    #pragma unroll
    for (int i = ty; i < 32; i += 8)
        tile[i][tx] = x[((size_t)b*HWN + n0 + i)*CCH + c0 + tx];
    __syncthreads();
    #pragma unroll
    for (int i = ty; i < 32; i += 8)
        x2d[((size_t)b*CCH + c0 + i)*HWN + n0 + tx] = tile[tx][i];
}

// ---------------- fused dual-conv 3x3 SAME, NCHW ----------------
// 16x32 spatial tile, 256 threads, 2 x-adjacent pixels per thread, CT couts/block.
// Two independent conv "parts" in one launch, selected by blockIdx.y.
// Part A may be split over cin into nChunksA chunks (chunk0 -> outA with bias,
// chunk1 -> outA2 without bias); consumer sums partials.
// act: 0 none, 1 exact GELU, 2 sigmoid
template<int CT>
__global__ void __launch_bounds__(256, 2) conv_fused(
    const float* __restrict__ inA, const float* __restrict__ wA,
    const float* __restrict__ bAp, float* __restrict__ outA, float* __restrict__ outA2,
    int CinA, int CoutA, int cinGA, int coutGA, int actA, int nChunksA, int nYA,
    const float* __restrict__ inB, const float* __restrict__ wB,
    const float* __restrict__ bBp, float* __restrict__ outB,
    int CinB, int CoutB, int cinGB, int coutGB, int actB)
{
    const int tid   = threadIdx.x;
    const int tx2   = tid & 15;           // thread col (covers x = 2*tx2, 2*tx2+1)
    const int ty    = tid >> 4;           // row 0..15
    const int sx    = blockIdx.x & 1;
    const int sy    = (blockIdx.x >> 1) & 3;
    const int b     = blockIdx.x >> 3;
    const int tileX = sx * 32;
    const int tileY = sy * 16;

    const float* in;  const float* wgt; const float* bias; float* out;
    int Cin, Cout, cinG, coutG, act, co0, ciOff, cinLen, addBias;

    int y = blockIdx.y;
    if (y < nYA) {
        int coPart = y / nChunksA;
        int chunk  = y - coPart * nChunksA;
        in = inA; wgt = wA; bias = bAp;
        Cin = CinA; Cout = CoutA; cinG = cinGA; coutG = coutGA; act = actA;
        cinLen = cinGA / nChunksA;
        ciOff  = chunk * cinLen;
        out    = chunk ? outA2 : outA;
        addBias = (chunk == 0);
        co0 = coPart * CT;
    } else {
        in = inB; wgt = wB; bias = bBp; out = outB;
        Cin = CinB; Cout = CoutB; cinG = cinGB; coutG = coutGB; act = actB;
        cinLen = cinGB; ciOff = 0; addBias = 1;
        co0 = (y - nYA) * CT;
    }
    const int grp    = co0 / coutG;
    const int ciBase = grp * cinG + ciOff;

    __shared__ float4 sIn[18*36];
    __shared__ float4 sW [CT*9];

    float acc[CT*2];
    #pragma unroll
    for (int i = 0; i < CT*2; i++) acc[i] = 0.f;

    for (int ci = 0; ci < cinLen; ci += 4) {
        const float* ip = in + ((size_t)(b*Cin + ciBase + ci))*HWN;
        for (int i = tid; i < 18*34; i += 256) {
            int yy = i / 34, xx = i - yy*34;
            int gy = tileY + yy - 1, gx = tileX + xx - 1;
            float4 v = make_float4(0.f,0.f,0.f,0.f);
            if (gy >= 0 && gy < HH && gx >= 0 && gx < WW) {
                const float* p = ip + gy*WW + gx;
                v.x = p[0]; v.y = p[HWN]; v.z = p[2*HWN]; v.w = p[3*HWN];
            }
            sIn[yy*36 + xx] = v;
        }
        if (tid < CT*9) {
            int co = tid / 9, k = tid - co*9;
            const float* wp = wgt + ((size_t)(co0+co)*cinG + ciOff + ci)*9 + k;
            sW[tid] = make_float4(wp[0], wp[9], wp[18], wp[27]);
        }
        __syncthreads();

        float4 r[12];
        #pragma unroll
        for (int dy = 0; dy < 3; dy++)
            #pragma unroll
            for (int dx = 0; dx < 4; dx++)
                r[dy*4+dx] = sIn[(ty+dy)*36 + 2*tx2 + dx];

        #pragma unroll
        for (int co = 0; co < CT; co++) {
            float a0 = acc[2*co], a1 = acc[2*co+1];
            #pragma unroll
            for (int dy = 0; dy < 3; dy++)
                #pragma unroll
                for (int dx = 0; dx < 3; dx++) {
                    float4 w  = sW[co*9 + dy*3 + dx];
                    float4 i0 = r[dy*4 + dx];
                    float4 i1 = r[dy*4 + dx + 1];
                    a0 += i0.x*w.x; a1 += i1.x*w.x;
                    a0 += i0.y*w.y; a1 += i1.y*w.y;
                    a0 += i0.z*w.z; a1 += i1.z*w.z;
                    a0 += i0.w*w.w; a1 += i1.w*w.w;
                }
            acc[2*co] = a0; acc[2*co+1] = a1;
        }
        __syncthreads();
    }

    const int oy = tileY + ty, ox = tileX + 2*tx2;
    #pragma unroll
    for (int co = 0; co < CT; co++) {
        float bv = addBias ? bias[co0 + co] : 0.f;
        float v0 = acc[2*co]   + bv;
        float v1 = acc[2*co+1] + bv;
        if (act == 1)      { v0 = v0 * normcdff(v0); v1 = v1 * normcdff(v1); }
        else if (act == 2) { v0 = 1.f/(1.f+expf(-v0)); v1 = 1.f/(1.f+expf(-v1)); }
        float2 o = make_float2(v0, v1);
        *reinterpret_cast<float2*>(&out[(((size_t)b*Cout + co0 + co)*HH + oy)*WW + ox]) = o;
    }
}

// ---------------- deformable sampling + modulation + mean over P ----------------
__global__ void __launch_bounds__(256) sample_kernel(
    const float* __restrict__ x,     // [B, HW, C] native
    const float* __restrict__ off,   // partial 1 [B,72,HW]
    const float* __restrict__ off2,  // partial 2 [B,72,HW]
    const float* __restrict__ mod,   // [B,36,HW]
    float* __restrict__ out)         // [B, HW, C]
{
    const int t   = threadIdx.x;
    const int c   = t & 63;
    const int pl  = t >> 6;
    const int pix = blockIdx.x * 4 + pl;
    const int g   = blockIdx.y;
    const int b   = blockIdx.z;
    const int yq  = pix >> 6;
    const int xq  = pix & 63;

    const float* offp  = off  + ((size_t)b*72 + g*18)*HWN + pix;
    const float* offp2 = off2 + ((size_t)b*72 + g*18)*HWN + pix;
    const float* modp  = mod  + ((size_t)b*36 + g*9 )*HWN + pix;
    const float* xb    = x    + (size_t)b*HWN*CCH + g*CG + c;

    float acc = 0.f;
    #pragma unroll
    for (int p = 0; p < 9; p++) {
        float ox = offp[(size_t)p*HWN]     + offp2[(size_t)p*HWN];
        float oy = offp[(size_t)(9+p)*HWN] + offp2[(size_t)(9+p)*HWN];
        float mv = modp[(size_t)p*HWN];

        float px = fminf(fmaxf((float)(xq + (p%3) - 1) + ox, 0.f), (float)(WW-1));
        float py = fminf(fmaxf((float)(yq + (p/3) - 1) + oy, 0.f), (float)(HH-1));

        float x0f = floorf(px), y0f = floorf(py);
        float wx = px - x0f, wy = py - y0f;
        int x0 = (int)x0f, y0 = (int)y0f;
        int x1 = min(x0 + 1, WW-1);
        int y1 = min(y0 + 1, HH-1);

        float v00 = xb[(size_t)(y0*WW + x0)*CCH];
        float v01 = xb[(size_t)(y0*WW + x1)*CCH];
        float v10 = xb[(size_t)(y1*WW + x0)*CCH];
        float v11 = xb[(size_t)(y1*WW + x1)*CCH];

        float top = v00 + wx*(v01 - v00);
        float bot = v10 + wx*(v11 - v10);
        acc += (top + wy*(bot - top)) * mv;
    }
    out[((size_t)b*HWN + pix)*CCH + g*CG + c] = acc * (1.f/9.f);
}

// ---------------- launch ----------------
extern "C" void kernel_launch(void* const* d_in, const int* in_sizes, int n_in,
                              void* d_out, int out_size)
{
    const float* x      = (const float*)d_in[0];
    const float* off_w1 = (const float*)d_in[1];
    const float* off_b1 = (const float*)d_in[2];
    const float* off_w2 = (const float*)d_in[3];
    const float* off_b2 = (const float*)d_in[4];
    const float* mod_w1 = (const float*)d_in[5];
    const float* mod_b1 = (const float*)d_in[6];
    const float* mod_w2 = (const float*)d_in[7];
    const float* mod_b2 = (const float*)d_in[8];
    float* out = (float*)d_out;

    float* x2d;  cudaGetSymbolAddress((void**)&x2d,  g_x2d);
    float* h;    cudaGetSymbolAddress((void**)&h,    g_h);
    float* off;  cudaGetSymbolAddress((void**)&off,  g_off);
    float* off2; cudaGetSymbolAddress((void**)&off2, g_off2);
    float* m;    cudaGetSymbolAddress((void**)&m,    g_m);
    float* md;   cudaGetSymbolAddress((void**)&md,   g_mod);

    // 1) transpose
    {
        dim3 grid(HWN/32, CCH/32, BSZ), blk(32, 8);
        transpose_kernel<<<grid, blk>>>(x, x2d);
    }
    // 2) stage 1: mod1 (A: 64<-256, GELU, long blocks first) + off1 (B: grouped 256<-256, GELU)
    {
        dim3 grid(32, 4 + 16);
        conv_fused<16><<<grid, 256>>>(
            x2d, mod_w1, mod_b1, m, nullptr, 256, 64, 256, 64, 1, 1, 4,
            x2d, off_w1, off_b1, h, 256, 256, 64, 64, 1);
    }
    // 3) stage 2: off2 (A: 72<-256, none, split cin x2) + mod2 (B: 36<-64, sigmoid)
    {
        dim3 grid(32, 12 + 3);
        conv_fused<12><<<grid, 256>>>(
            h, off_w2, off_b2, off, off2, 256, 72, 256, 72, 0, 2, 12,
            m, mod_w2, mod_b2, md, 64, 36, 64, 36, 2);
    }
    // 4) sampling
    {
        dim3 grid(HWN/4, GG, BSZ);
        sample_kernel<<<grid, 256>>>(x, off, off2, md, out);
    }
}

// round 3
// speedup vs baseline: 1.5100x; 1.1425x over previous
#include <cuda_runtime.h>
#include <cuda_bf16.h>

#define BSZ 4
#define CCH 256
#define HH 64
#define WW 64
#define HWN (HH*WW)          // 4096
#define GG 4
#define CG (CCH/GG)          // 64

typedef unsigned long long ull;

// ---------------- f32x2 packed-fp32 helpers (sm_100+; ptxas never emits these) ----------------
#define FMA2(d, a, b) asm("fma.rn.f32x2 %0, %1, %2, %3;" : "=l"(d) : "l"(a), "l"(b), "l"(d))
#define BCAST2(d, f)  asm("mov.b64 %0, {%1, %1};" : "=l"(d) : "f"(f))
#define UNPK2(lo, hi, v) asm("mov.b64 {%0, %1}, %2;" : "=f"(lo), "=f"(hi) : "l"(v))

__device__ __forceinline__ ull pk2(float lo, float hi) {
    return (ull)__float_as_uint(lo) | ((ull)__float_as_uint(hi) << 32);
}

// ---------------- scratch ----------------
__device__ float g_x2d [BSZ * CCH * HWN];
__device__ float g_h   [BSZ * CCH * HWN];
__device__ float g_off [BSZ * 72 * HWN];     // off2 partial (cin 0..127, + bias)
__device__ float g_off2[BSZ * 72 * HWN];     // off2 partial (cin 128..255)
__device__ float g_m   [BSZ * 64 * HWN];
__device__ float g_mod [BSZ * 36 * HWN];

// ---------------- transpose [B,HW,C] -> [B,C,HW] ----------------
__global__ void transpose_kernel(const float* __restrict__ x, float* __restrict__ x2d) {
    __shared__ float tile[32][33];
    int b  = blockIdx.z;
    int n0 = blockIdx.x * 32;
    int c0 = blockIdx.y * 32;
    int tx = threadIdx.x, ty = threadIdx.y; // 32 x 8
    #pragma unroll
    for (int i = ty; i < 32; i += 8)
        tile[i][tx] = x[((size_t)b*HWN + n0 + i)*CCH + c0 + tx];
    __syncthreads();
    #pragma unroll
    for (int i = ty; i < 32; i += 8)
        x2d[((size_t)b*CCH + c0 + i)*HWN + n0 + tx] = tile[tx][i];
}

// ---------------- fused dual-conv 3x3 SAME, NCHW, f32x2 inner loop ----------------
// 16x32 spatial tile, 256 threads, 2 x-adjacent pixels/thread, CT couts/block
// (accumulated as CT/2 channel-PAIRS in packed f32x2 registers).
// Two independent convs per launch via blockIdx.y; part A may be cin-split.
template<int CT>
__global__ void __launch_bounds__(256, 2) conv_fused(
    const float* __restrict__ inA, const float* __restrict__ wA,
    const float* __restrict__ bAp, float* __restrict__ outA, float* __restrict__ outA2,
    int CinA, int CoutA, int cinGA, int coutGA, int actA, int nChunksA, int nYA,
    const float* __restrict__ inB, const float* __restrict__ wB,
    const float* __restrict__ bBp, float* __restrict__ outB,
    int CinB, int CoutB, int cinGB, int coutGB, int actB)
{
    constexpr int PAIRS = CT / 2;
    const int tid   = threadIdx.x;
    const int tx2   = tid & 15;
    const int ty    = tid >> 4;
    const int sx    = blockIdx.x & 1;
    const int sy    = (blockIdx.x >> 1) & 3;
    const int b     = blockIdx.x >> 3;
    const int tileX = sx * 32;
    const int tileY = sy * 16;

    const float* in;  const float* wgt; const float* bias; float* out;
    int Cin, Cout, cinG, coutG, act, co0, ciOff, cinLen, addBias;

    int y = blockIdx.y;
    if (y < nYA) {
        int coPart = y / nChunksA;
        int chunk  = y - coPart * nChunksA;
        in = inA; wgt = wA; bias = bAp;
        Cin = CinA; Cout = CoutA; cinG = cinGA; coutG = coutGA; act = actA;
        cinLen = cinGA / nChunksA;
        ciOff  = chunk * cinLen;
        out    = chunk ? outA2 : outA;
        addBias = (chunk == 0);
        co0 = coPart * CT;
    } else {
        in = inB; wgt = wB; bias = bBp; out = outB;
        Cin = CinB; Cout = CoutB; cinG = cinGB; coutG = coutGB; act = actB;
        cinLen = cinGB; ciOff = 0; addBias = 1;
        co0 = (y - nYA) * CT;
    }
    const int grp    = co0 / coutG;
    const int ciBase = grp * cinG + ciOff;

    __shared__ float4     sIn[18*36];
    __shared__ ulonglong2 sW [9*2*PAIRS];   // [(k*2+half)*PAIRS + pair] = packed co-pair weights

    ull acc[PAIRS][2];
    #pragma unroll
    for (int i = 0; i < PAIRS; i++) { acc[i][0] = 0ull; acc[i][1] = 0ull; }

    for (int ci = 0; ci < cinLen; ci += 4) {
        const float* ip = in + ((size_t)(b*Cin + ciBase + ci))*HWN;
        for (int i = tid; i < 18*34; i += 256) {
            int yy = i / 34, xx = i - yy*34;
            int gy = tileY + yy - 1, gx = tileX + xx - 1;
            float4 v = make_float4(0.f,0.f,0.f,0.f);
            if (gy >= 0 && gy < HH && gx >= 0 && gx < WW) {
                const float* p = ip + gy*WW + gx;
                v.x = p[0]; v.y = p[HWN]; v.z = p[2*HWN]; v.w = p[3*HWN];
            }
            sIn[yy*36 + xx] = v;
        }
        // packed weights: entry (k, half h, pair pr):
        //   .x = (wL[cin0], wR[cin0])  .y = (wL[cin0+1], wR[cin0+1]),  cin0 = ci + 2h
        if (tid < 9*2*PAIRS) {
            int k   = tid / (2*PAIRS);
            int rem = tid - k*(2*PAIRS);
            int h   = rem / PAIRS;
            int pr  = rem - h*PAIRS;
            int coL = co0 + 2*pr;
            const float* w0 = wgt + ((size_t)coL*cinG + ciOff + ci + 2*h)*9 + k;
            const float* w1 = wgt + ((size_t)(coL+1)*cinG + ciOff + ci + 2*h)*9 + k;
            ulonglong2 e;
            e.x = pk2(w0[0], w1[0]);
            e.y = pk2(w0[9], w1[9]);
            sW[tid] = e;
        }
        __syncthreads();

        #pragma unroll
        for (int k = 0; k < 9; k++) {
            const int dy = k / 3, dx = k - 3*(k/3);
            float4 i0 = sIn[(ty+dy)*36 + 2*tx2 + dx];
            float4 i1 = sIn[(ty+dy)*36 + 2*tx2 + dx + 1];
            ull b0x,b0y,b0z,b0w, b1x,b1y,b1z,b1w;
            BCAST2(b0x, i0.x); BCAST2(b0y, i0.y); BCAST2(b0z, i0.z); BCAST2(b0w, i0.w);
            BCAST2(b1x, i1.x); BCAST2(b1y, i1.y); BCAST2(b1z, i1.z); BCAST2(b1w, i1.w);
            #pragma unroll
            for (int pr = 0; pr < PAIRS; pr++) {
                ulonglong2 w01 = sW[(k*2  )*PAIRS + pr];   // cin 0,1
                ulonglong2 w23 = sW[(k*2+1)*PAIRS + pr];   // cin 2,3
                FMA2(acc[pr][0], w01.x, b0x);
                FMA2(acc[pr][1], w01.x, b1x);
                FMA2(acc[pr][0], w01.y, b0y);
                FMA2(acc[pr][1], w01.y, b1y);
                FMA2(acc[pr][0], w23.x, b0z);
                FMA2(acc[pr][1], w23.x, b1z);
                FMA2(acc[pr][0], w23.y, b0w);
                FMA2(acc[pr][1], w23.y, b1w);
            }
        }
        __syncthreads();
    }

    const int oy = tileY + ty, ox = tileX + 2*tx2;
    #pragma unroll
    for (int pr = 0; pr < PAIRS; pr++) {
        float vL0, vH0, vL1, vH1;
        UNPK2(vL0, vH0, acc[pr][0]);   // pixel0: couts 2pr, 2pr+1
        UNPK2(vL1, vH1, acc[pr][1]);   // pixel1
        int coL = co0 + 2*pr;
        float bL = addBias ? bias[coL]   : 0.f;
        float bH = addBias ? bias[coL+1] : 0.f;
        float a0 = vL0 + bL, a1 = vL1 + bL;
        float c0 = vH0 + bH, c1 = vH1 + bH;
        if (act == 1) {
            a0 = a0 * normcdff(a0); a1 = a1 * normcdff(a1);
            c0 = c0 * normcdff(c0); c1 = c1 * normcdff(c1);
        } else if (act == 2) {
            a0 = 1.f/(1.f+expf(-a0)); a1 = 1.f/(1.f+expf(-a1));
            c0 = 1.f/(1.f+expf(-c0)); c1 = 1.f/(1.f+expf(-c1));
        }
        *reinterpret_cast<float2*>(&out[(((size_t)b*Cout + coL  )*HH + oy)*WW + ox]) = make_float2(a0, a1);
        *reinterpret_cast<float2*>(&out[(((size_t)b*Cout + coL+1)*HH + oy)*WW + ox]) = make_float2(c0, c1);
    }
}

// ---------------- deformable sampling: per-(pixel,p) prep in smem, then gather ----------------
// Block = 4 pixels x 64 channels (one group). First 36 threads compute bilinear
// corner weights (premultiplied by mod/9) and 4 premultiplied element offsets.
__global__ void __launch_bounds__(256) sample_kernel(
    const float* __restrict__ x,     // [B, HW, C] native
    const float* __restrict__ off,   // partial 1 [B,72,HW]
    const float* __restrict__ off2,  // partial 2 [B,72,HW]
    const float* __restrict__ mod,   // [B,36,HW]
    float* __restrict__ out)         // [B, HW, C]
{
    __shared__ float4 sw[36];
    __shared__ int4   so[36];

    const int t    = threadIdx.x;
    const int c    = t & 63;
    const int pl   = t >> 6;
    const int pix0 = blockIdx.x * 4;
    const int g    = blockIdx.y;
    const int b    = blockIdx.z;

    if (t < 36) {
        const int pli = t / 9;
        const int p   = t - pli * 9;
        const int pix = pix0 + pli;
        const int yq  = pix >> 6;
        const int xq  = pix & 63;

        const float* offp  = off  + ((size_t)b*72 + g*18)*HWN + pix;
        const float* offp2 = off2 + ((size_t)b*72 + g*18)*HWN + pix;
        const float* modp  = mod  + ((size_t)b*36 + g*9 )*HWN + pix;

        float ox = offp[(size_t)p*HWN]     + offp2[(size_t)p*HWN];
        float oy = offp[(size_t)(9+p)*HWN] + offp2[(size_t)(9+p)*HWN];
        float mv = modp[(size_t)p*HWN] * (1.f/9.f);

        float px = fminf(fmaxf((float)(xq + (p%3) - 1) + ox, 0.f), (float)(WW-1));
        float py = fminf(fmaxf((float)(yq + (p/3) - 1) + oy, 0.f), (float)(HH-1));

        float x0f = floorf(px), y0f = floorf(py);
        float wx = px - x0f, wy = py - y0f;
        int x0 = (int)x0f, y0 = (int)y0f;
        int x1 = min(x0 + 1, WW-1);
        int y1 = min(y0 + 1, HH-1);

        sw[t] = make_float4((1.f-wx)*(1.f-wy)*mv, wx*(1.f-wy)*mv,
                            (1.f-wx)*wy*mv,       wx*wy*mv);
        so[t] = make_int4((y0*WW + x0)*CCH, (y0*WW + x1)*CCH,
                          (y1*WW + x0)*CCH, (y1*WW + x1)*CCH);
    }
    __syncthreads();

    const float* xb = x + (size_t)b*HWN*CCH + g*CG + c;
    float acc = 0.f;
    #pragma unroll
    for (int p = 0; p < 9; p++) {
        float4 w = sw[pl*9 + p];
        int4   o = so[pl*9 + p];
        float v00 = __ldg(xb + o.x);
        float v01 = __ldg(xb + o.y);
        float v10 = __ldg(xb + o.z);
        float v11 = __ldg(xb + o.w);
        acc += v00*w.x + v01*w.y + v10*w.z + v11*w.w;
    }
    out[((size_t)b*HWN + pix0 + pl)*CCH + g*CG + c] = acc;
}

// ---------------- launch ----------------
extern "C" void kernel_launch(void* const* d_in, const int* in_sizes, int n_in,
                              void* d_out, int out_size)
{
    const float* x      = (const float*)d_in[0];
    const float* off_w1 = (const float*)d_in[1];
    const float* off_b1 = (const float*)d_in[2];
    const float* off_w2 = (const float*)d_in[3];
    const float* off_b2 = (const float*)d_in[4];
    const float* mod_w1 = (const float*)d_in[5];
    const float* mod_b1 = (const float*)d_in[6];
    const float* mod_w2 = (const float*)d_in[7];
    const float* mod_b2 = (const float*)d_in[8];
    float* out = (float*)d_out;

    float* x2d;  cudaGetSymbolAddress((void**)&x2d,  g_x2d);
    float* h;    cudaGetSymbolAddress((void**)&h,    g_h);
    float* off;  cudaGetSymbolAddress((void**)&off,  g_off);
    float* off2; cudaGetSymbolAddress((void**)&off2, g_off2);
    float* m;    cudaGetSymbolAddress((void**)&m,    g_m);
    float* md;   cudaGetSymbolAddress((void**)&md,   g_mod);

    // 1) transpose
    {
        dim3 grid(HWN/32, CCH/32, BSZ), blk(32, 8);
        transpose_kernel<<<grid, blk>>>(x, x2d);
    }
    // 2) stage 1: mod1 (A: 64<-256, GELU) + off1 (B: grouped 256<-256, GELU)
    {
        dim3 grid(32, 4 + 16);
        conv_fused<16><<<grid, 256>>>(
            x2d, mod_w1, mod_b1, m, nullptr, 256, 64, 256, 64, 1, 1, 4,
            x2d, off_w1, off_b1, h, 256, 256, 64, 64, 1);
    }
    // 3) stage 2: off2 (A: 72<-256, none, cin-split x2) + mod2 (B: 36<-64, sigmoid)
    {
        dim3 grid(32, 12 + 3);
        conv_fused<12><<<grid, 256>>>(
            h, off_w2, off_b2, off, off2, 256, 72, 256, 72, 0, 2, 12,
            m, mod_w2, mod_b2, md, 64, 36, 64, 36, 2);
    }
    // 4) sampling
    {
        dim3 grid(HWN/4, GG, BSZ);
        sample_kernel<<<grid, 256>>>(x, off, off2, md, out);
    }
}

// round 6
// speedup vs baseline: 1.8353x; 1.2154x over previous
#include <cuda_runtime.h>
#include <cuda_bf16.h>
#include <cstdint>

#define BSZ 4
#define CCH 256
#define HH 64
#define WW 64
#define HWN 4096
#define GG 4
#define CG 64

// ---------------- warp-MMA helpers (base-target ISA: sm_80+, compiles for compute_103) --------
__device__ __forceinline__ uint32_t smem_u32(const void* p){
  uint32_t a; asm("{ .reg .u64 t; cvta.to.shared.u64 t, %1; cvt.u32.u64 %0, t; }" : "=r"(a) : "l"(p)); return a;
}
__device__ __forceinline__ void ldsm_x4(uint32_t* r, uint32_t a) {
    asm volatile("ldmatrix.sync.aligned.m8n8.x4.shared.b16 {%0,%1,%2,%3}, [%4];"
        : "=r"(r[0]), "=r"(r[1]), "=r"(r[2]), "=r"(r[3]) : "r"(a));
}
__device__ __forceinline__ void ldsm_x2(uint32_t* r, uint32_t a) {
    asm volatile("ldmatrix.sync.aligned.m8n8.x2.shared.b16 {%0,%1}, [%2];"
        : "=r"(r[0]), "=r"(r[1]) : "r"(a));
}
__device__ __forceinline__ void mma_bf16(float* d, const uint32_t* a, uint32_t b0, uint32_t b1) {
    asm volatile("mma.sync.aligned.m16n8k16.row.col.f32.bf16.bf16.f32 "
        "{%0,%1,%2,%3}, {%4,%5,%6,%7}, {%8,%9}, {%0,%1,%2,%3};"
        : "+f"(d[0]), "+f"(d[1]), "+f"(d[2]), "+f"(d[3])
        : "r"(a[0]), "r"(a[1]), "r"(a[2]), "r"(a[3]), "r"(b0), "r"(b1));
}

// ---------------- scratch ----------------
__device__ float g_x2d [BSZ * CCH * HWN];
__device__ float g_h   [BSZ * CCH * HWN];
__device__ float g_m   [BSZ * 64  * HWN];
__device__ float g_off [BSZ * 72  * HWN];
__device__ float g_mod [BSZ * 36  * HWN];

// prepacked bf16 hi/lo weights, layout per part: [chunk = cb*9+tap][Npad][32]
// off1: 4 groups x 36864 = 147456 | mod1: 147456 | off2: 165888 | mod2(Npad 72): 41472
#define W_TOTAL 502272
__device__ __nv_bfloat16 g_wHi[W_TOTAL];
__device__ __nv_bfloat16 g_wLo[W_TOTAL];

// ---------------- transpose [B,HW,C] -> [B,C,HW] ----------------
__global__ void transpose_kernel(const float* __restrict__ x, float* __restrict__ x2d) {
    __shared__ float tile[32][33];
    int b  = blockIdx.z;
    int n0 = blockIdx.x * 32;
    int c0 = blockIdx.y * 32;
    int tx = threadIdx.x, ty = threadIdx.y;
    #pragma unroll
    for (int i = ty; i < 32; i += 8)
        tile[i][tx] = x[((size_t)b*HWN + n0 + i)*CCH + c0 + tx];
    __syncthreads();
    #pragma unroll
    for (int i = ty; i < 32; i += 8)
        x2d[((size_t)b*CCH + c0 + i)*HWN + n0 + tx] = tile[tx][i];
}

// ---------------- weight prepack (fp32 -> bf16 hi/lo split) ----------------
struct PackPart { const float* w; int dstBase, Cout, Npad, cinG, groups, elemsPerG; };

__global__ void prepack_kernel(PackPart p0, PackPart p1, PackPart p2, PackPart p3) {
    PackPart ps[4] = {p0, p1, p2, p3};
    long e = (long)blockIdx.x * 256 + threadIdx.x;
    int q = 0;
    for (; q < 4; q++) { long t = (long)ps[q].groups * ps[q].elemsPerG; if (e < t) break; e -= t; }
    if (q >= 4) return;
    PackPart pp = ps[q];
    int g  = (int)(e / pp.elemsPerG);
    int e2 = (int)(e - (long)g * pp.elemsPerG);
    int chunk = e2 / (pp.Npad * 32);
    int r     = e2 - chunk * (pp.Npad * 32);
    int n = r >> 5, j = r & 31;
    int cb = chunk / 9, tap = chunk - cb * 9;
    float v = 0.f;
    if (n < pp.Cout)
        v = pp.w[(((size_t)(g * pp.Cout + n)) * pp.cinG + cb * 32 + j) * 9 + tap];
    __nv_bfloat16 h = __float2bfloat16(v);
    long dst = pp.dstBase + (long)g * pp.elemsPerG + e2;
    g_wHi[dst] = h;
    g_wLo[dst] = __float2bfloat16(v - __bfloat162float(h));
}

// ---------------- implicit-GEMM conv via mma.sync (bf16x2 split, fp32 accum) ----------------
struct ConvPart {
    const float* in; const __nv_bfloat16* wHi; const __nv_bfloat16* wLo;
    const float* bias; float* out;
    int cinTotal, ciBase, coutTotal, coutBase, Cout, nCb, act;
};
struct ConvArgs { ConvPart p[5]; };

// smem layout (bytes): A patches [4 rows][66 cols][32 ch] bf16, 80B pixel pitch
#define SM_A_HI 0
#define SM_A_LO 21120
#define SM_B    42240
#define B_BUF   5760            // 72 n-rows x 80B
#define SM_TOT  (42240 + 4*5760)   // 65280

template<int NFR>  // n-fragments of 8; Npad = NFR*8
__device__ __forceinline__ void stage_b(char* smem, const __nv_bfloat16* wHi,
                                        const __nv_bfloat16* wLo, int chunk, int par, int tid) {
    const int nv = NFR * 32;  // uint4 per hi/lo array
    const uint4* sH = (const uint4*)(wHi + (size_t)chunk * (NFR * 8 * 32));
    const uint4* sL = (const uint4*)(wLo + (size_t)chunk * (NFR * 8 * 32));
    for (int i = tid; i < 2 * nv; i += 256) {
        int arr = (i >= nv);
        int ii  = arr ? i - nv : i;
        uint4 v = arr ? sL[ii] : sH[ii];
        int n = ii >> 2, qq = ii & 3;
        *(uint4*)(smem + SM_B + (size_t)(par * 2 + arr) * B_BUF + n * 80 + qq * 16) = v;
    }
}

template<int NFR>
__global__ void __launch_bounds__(256) conv_mma(ConvArgs args) {
    extern __shared__ char smem[];
    const ConvPart P = args.p[blockIdx.y];
    const int tid = threadIdx.x;
    const int wid = tid >> 5, lid = tid & 31;
    const int b  = blockIdx.x >> 5;
    const int r0 = (blockIdx.x & 31) << 1;    // 2 image rows -> 128 pixels
    uint32_t sb = smem_u32(smem);

    float acc[NFR][4];
    #pragma unroll
    for (int i = 0; i < NFR; i++) { acc[i][0]=acc[i][1]=acc[i][2]=acc[i][3]=0.f; }

    // lane-constant fragment addressing
    const int m    = wid * 16 + (lid & 15);
    const int yloc = m >> 6, xpix = m & 63;
    const uint32_t aBase  = (uint32_t)(((yloc + 1) * 66 + (xpix + 1)) * 80) + ((lid >> 4) * 16);
    const int nloc4  = (lid & 7) + ((lid >> 4) << 3);
    const int khalfB = ((lid >> 3) & 1) * 16;

    #pragma unroll 1
    for (int cb = 0; cb < P.nCb; cb++) {
        __syncthreads();
        // stage A patch: [4 rows x 66 cols x 32 ch] fp32 -> bf16 hi/lo
        const float* ip = P.in + (size_t)(b * P.cinTotal + P.ciBase + cb * 32) * HWN;
        #pragma unroll 1
        for (int i = tid; i < 4 * 66 * 32; i += 256) {
            int j   = i / 264;
            int pix = i - j * 264;
            int py = pix / 66, px = pix - py * 66;
            int y = r0 - 1 + py, x = px - 1;
            float v = 0.f;
            if ((unsigned)y < HH && (unsigned)x < WW) v = ip[(size_t)j * HWN + y * WW + x];
            __nv_bfloat16 h = __float2bfloat16(v);
            __nv_bfloat16 l = __float2bfloat16(v - __bfloat162float(h));
            uint32_t o = (uint32_t)(py * 66 + px) * 80 + j * 2;
            *(__nv_bfloat16*)(smem + SM_A_HI + o) = h;
            *(__nv_bfloat16*)(smem + SM_A_LO + o) = l;
        }
        stage_b<NFR>(smem, P.wHi, P.wLo, cb * 9, 0, tid);

        #pragma unroll 1
        for (int tap = 0; tap < 9; tap++) {
            __syncthreads();
            if (tap < 8) stage_b<NFR>(smem, P.wHi, P.wLo, cb * 9 + tap + 1, (tap + 1) & 1, tid);
            const int dy = tap / 3 - 1, dx = tap % 3 - 1;
            const uint32_t aOfs  = aBase + (dy * 66 + dx) * 80;
            const uint32_t bBase = sb + SM_B + (uint32_t)((tap & 1) * 2) * B_BUF;
            #pragma unroll
            for (int k16 = 0; k16 < 2; k16++) {
                uint32_t ah[4], al[4];
                ldsm_x4(ah, sb + SM_A_HI + aOfs + k16 * 32);
                ldsm_x4(al, sb + SM_A_LO + aOfs + k16 * 32);
                #pragma unroll
                for (int nf2 = 0; nf2 < NFR / 2; nf2++) {
                    uint32_t bAddr = bBase + (uint32_t)(nf2 * 16 + nloc4) * 80 + k16 * 32 + khalfB;
                    uint32_t bh[4], bl[4];
                    ldsm_x4(bh, bAddr);
                    ldsm_x4(bl, bAddr + B_BUF);
                    mma_bf16(acc[nf2*2],   ah, bh[0], bh[1]);
                    mma_bf16(acc[nf2*2+1], ah, bh[2], bh[3]);
                    mma_bf16(acc[nf2*2],   al, bh[0], bh[1]);
                    mma_bf16(acc[nf2*2+1], al, bh[2], bh[3]);
                    mma_bf16(acc[nf2*2],   ah, bl[0], bl[1]);
                    mma_bf16(acc[nf2*2+1], ah, bl[2], bl[3]);
                }
                if (NFR & 1) {
                    const int nf = NFR - 1;
                    uint32_t bAddr = bBase + (uint32_t)(nf * 8 + (lid & 7)) * 80 + k16 * 32 + khalfB;
                    uint32_t bh[2], bl[2];
                    ldsm_x2(bh, bAddr);
                    ldsm_x2(bl, bAddr + B_BUF);
                    mma_bf16(acc[nf], ah, bh[0], bh[1]);
                    mma_bf16(acc[nf], al, bh[0], bh[1]);
                    mma_bf16(acc[nf], ah, bl[0], bl[1]);
                }
            }
        }
    }

    // epilogue: transpose through smem for coalesced stores
    __syncthreads();
    float* sd = (float*)smem;           // overlay A region: [n][132] floats
    {
        const int rr = lid >> 2, cc = (lid & 3) * 2;
        const int mB = wid * 16;
        #pragma unroll
        for (int nf = 0; nf < NFR; nf++) {
            int n = nf * 8 + cc;
            sd[(n    ) * 132 + mB + rr    ] = acc[nf][0];
            sd[(n + 1) * 132 + mB + rr    ] = acc[nf][1];
            sd[(n    ) * 132 + mB + rr + 8] = acc[nf][2];
            sd[(n + 1) * 132 + mB + rr + 8] = acc[nf][3];
        }
    }
    __syncthreads();
    const int pixBase = r0 * WW;
    for (int i = tid; i < P.Cout * 128; i += 256) {
        int n = i >> 7, mm = i & 127;
        float v = sd[n * 132 + mm] + P.bias[n];
        if (P.act == 1)      v = v * normcdff(v);
        else if (P.act == 2) v = 1.f / (1.f + expf(-v));
        P.out[((size_t)(b * P.coutTotal + P.coutBase + n)) * HWN + pixBase + mm] = v;
    }
}

// ---------------- deformable sampling ----------------
__global__ void __launch_bounds__(256) sample_kernel(
    const float* __restrict__ x,     // [B, HW, C] native
    const float* __restrict__ off,   // [B,72,HW]
    const float* __restrict__ mod,   // [B,36,HW]
    float* __restrict__ out)         // [B, HW, C]
{
    __shared__ float4 sw[36];
    __shared__ int4   so[36];

    const int t    = threadIdx.x;
    const int c    = t & 63;
    const int pl   = t >> 6;
    const int pix0 = blockIdx.x * 4;
    const int g    = blockIdx.y;
    const int b    = blockIdx.z;

    if (t < 36) {
        const int pli = t / 9;
        const int p   = t - pli * 9;
        const int pix = pix0 + pli;
        const int yq  = pix >> 6;
        const int xq  = pix & 63;

        const float* offp = off + ((size_t)b*72 + g*18)*HWN + pix;
        const float* modp = mod + ((size_t)b*36 + g*9 )*HWN + pix;

        float ox = offp[(size_t)p*HWN];
        float oy = offp[(size_t)(9+p)*HWN];
        float mv = modp[(size_t)p*HWN] * (1.f/9.f);

        float px = fminf(fmaxf((float)(xq + (p%3) - 1) + ox, 0.f), (float)(WW-1));
        float py = fminf(fmaxf((float)(yq + (p/3) - 1) + oy, 0.f), (float)(HH-1));

        float x0f = floorf(px), y0f = floorf(py);
        float wx = px - x0f, wy = py - y0f;
        int x0 = (int)x0f, y0 = (int)y0f;
        int x1 = min(x0 + 1, WW-1);
        int y1 = min(y0 + 1, HH-1);

        sw[t] = make_float4((1.f-wx)*(1.f-wy)*mv, wx*(1.f-wy)*mv,
                            (1.f-wx)*wy*mv,       wx*wy*mv);
        so[t] = make_int4((y0*WW + x0)*CCH, (y0*WW + x1)*CCH,
                          (y1*WW + x0)*CCH, (y1*WW + x1)*CCH);
    }
    __syncthreads();

    const float* xb = x + (size_t)b*HWN*CCH + g*CG + c;
    float acc = 0.f;
    #pragma unroll
    for (int p = 0; p < 9; p++) {
        float4 w = sw[pl*9 + p];
        int4   o = so[pl*9 + p];
        float v00 = __ldg(xb + o.x);
        float v01 = __ldg(xb + o.y);
        float v10 = __ldg(xb + o.z);
        float v11 = __ldg(xb + o.w);
        acc += v00*w.x + v01*w.y + v10*w.z + v11*w.w;
    }
    out[((size_t)b*HWN + pix0 + pl)*CCH + g*CG + c] = acc;
}

// ---------------- launch ----------------
extern "C" void kernel_launch(void* const* d_in, const int* in_sizes, int n_in,
                              void* d_out, int out_size)
{
    const float* x      = (const float*)d_in[0];
    const float* off_w1 = (const float*)d_in[1];
    const float* off_b1 = (const float*)d_in[2];
    const float* off_w2 = (const float*)d_in[3];
    const float* off_b2 = (const float*)d_in[4];
    const float* mod_w1 = (const float*)d_in[5];
    const float* mod_b1 = (const float*)d_in[6];
    const float* mod_w2 = (const float*)d_in[7];
    const float* mod_b2 = (const float*)d_in[8];
    float* out = (float*)d_out;

    float *x2d, *h, *m, *off, *md;
    cudaGetSymbolAddress((void**)&x2d, g_x2d);
    cudaGetSymbolAddress((void**)&h,   g_h);
    cudaGetSymbolAddress((void**)&m,   g_m);
    cudaGetSymbolAddress((void**)&off, g_off);
    cudaGetSymbolAddress((void**)&md,  g_mod);

    __nv_bfloat16 *wHi, *wLo;
    cudaGetSymbolAddress((void**)&wHi, g_wHi);
    cudaGetSymbolAddress((void**)&wLo, g_wLo);

    cudaFuncSetAttribute(conv_mma<8>, cudaFuncAttributeMaxDynamicSharedMemorySize, SM_TOT);
    cudaFuncSetAttribute(conv_mma<9>, cudaFuncAttributeMaxDynamicSharedMemorySize, SM_TOT);

    // 1) transpose
    {
        dim3 grid(HWN/32, CCH/32, BSZ), blk(32, 8);
        transpose_kernel<<<grid, blk>>>(x, x2d);
    }
    // 2) weight prepack
    {
        PackPart p0; p0.w = off_w1; p0.dstBase = 0;      p0.Cout = 64; p0.Npad = 64; p0.cinG = 64;  p0.groups = 4; p0.elemsPerG = 2*9*64*32;   // 36864
        PackPart p1; p1.w = mod_w1; p1.dstBase = 147456; p1.Cout = 64; p1.Npad = 64; p1.cinG = 256; p1.groups = 1; p1.elemsPerG = 8*9*64*32;   // 147456
        PackPart p2; p2.w = off_w2; p2.dstBase = 294912; p2.Cout = 72; p2.Npad = 72; p2.cinG = 256; p2.groups = 1; p2.elemsPerG = 8*9*72*32;   // 165888
        PackPart p3; p3.w = mod_w2; p3.dstBase = 460800; p3.Cout = 36; p3.Npad = 72; p3.cinG = 64;  p3.groups = 1; p3.elemsPerG = 2*9*72*32;   // 41472
        long total = 4L*36864 + 147456 + 165888 + 41472;  // 502272
        prepack_kernel<<<(int)((total + 255)/256), 256>>>(p0, p1, p2, p3);
    }
    // 3) stage 1 (NFR=8): mod1 (long, first) + 4x off1 groups
    {
        ConvArgs a;
        ConvPart& M = a.p[0];
        M.in = x2d; M.wHi = wHi + 147456; M.wLo = wLo + 147456; M.bias = mod_b1; M.out = m;
        M.cinTotal = 256; M.ciBase = 0; M.coutTotal = 64; M.coutBase = 0;
        M.Cout = 64; M.nCb = 8; M.act = 1;
        for (int g = 0; g < 4; g++) {
            ConvPart& P = a.p[1 + g];
            P.in = x2d; P.wHi = wHi + (size_t)g*36864; P.wLo = wLo + (size_t)g*36864;
            P.bias = off_b1 + g*64; P.out = h;
            P.cinTotal = 256; P.ciBase = g*64; P.coutTotal = 256; P.coutBase = g*64;
            P.Cout = 64; P.nCb = 2; P.act = 1;
        }
        conv_mma<8><<<dim3(128, 5), 256, SM_TOT>>>(a);
    }
    // 4) stage 2 (NFR=9): off2 (long, first) + mod2 (Npad 72)
    {
        ConvArgs a;
        ConvPart& O = a.p[0];
        O.in = h; O.wHi = wHi + 294912; O.wLo = wLo + 294912; O.bias = off_b2; O.out = off;
        O.cinTotal = 256; O.ciBase = 0; O.coutTotal = 72; O.coutBase = 0;
        O.Cout = 72; O.nCb = 8; O.act = 0;
        ConvPart& Q = a.p[1];
        Q.in = m; Q.wHi = wHi + 460800; Q.wLo = wLo + 460800; Q.bias = mod_b2; Q.out = md;
        Q.cinTotal = 64; Q.ciBase = 0; Q.coutTotal = 36; Q.coutBase = 0;
        Q.Cout = 36; Q.nCb = 2; Q.act = 2;
        a.p[2] = a.p[1]; a.p[3] = a.p[1]; a.p[4] = a.p[1];  // unused
        conv_mma<9><<<dim3(128, 2), 256, SM_TOT>>>(a);
    }
    // 5) sampling
    {
        dim3 grid(HWN/4, GG, BSZ);
        sample_kernel<<<grid, 256>>>(x, off, md, out);
    }
}

// round 7
// speedup vs baseline: 2.1243x; 1.1574x over previous
#include <cuda_runtime.h>
#include <cuda_bf16.h>
#include <cstdint>

#define BSZ 4
#define CCH 256
#define HH 64
#define WW 64
#define HWN 4096
#define GG 4
#define CG 64

#define MP_STRIDE (BSZ*64*HWN)    // per mod1-partial buffer (floats)
#define OP_STRIDE (BSZ*72*HWN)    // per off2-partial buffer (floats)

// ---------------- warp-MMA helpers ----------------
__device__ __forceinline__ uint32_t smem_u32(const void* p){
  uint32_t a; asm("{ .reg .u64 t; cvta.to.shared.u64 t, %1; cvt.u32.u64 %0, t; }" : "=r"(a) : "l"(p)); return a;
}
__device__ __forceinline__ void ldsm_x4(uint32_t* r, uint32_t a) {
    asm volatile("ldmatrix.sync.aligned.m8n8.x4.shared.b16 {%0,%1,%2,%3}, [%4];"
        : "=r"(r[0]), "=r"(r[1]), "=r"(r[2]), "=r"(r[3]) : "r"(a));
}
__device__ __forceinline__ void ldsm_x2(uint32_t* r, uint32_t a) {
    asm volatile("ldmatrix.sync.aligned.m8n8.x2.shared.b16 {%0,%1}, [%2];"
        : "=r"(r[0]), "=r"(r[1]) : "r"(a));
}
__device__ __forceinline__ void mma_bf16(float* d, const uint32_t* a, uint32_t b0, uint32_t b1) {
    asm volatile("mma.sync.aligned.m16n8k16.row.col.f32.bf16.bf16.f32 "
        "{%0,%1,%2,%3}, {%4,%5,%6,%7}, {%8,%9}, {%0,%1,%2,%3};"
        : "+f"(d[0]), "+f"(d[1]), "+f"(d[2]), "+f"(d[3])
        : "r"(a[0]), "r"(a[1]), "r"(a[2]), "r"(a[3]), "r"(b0), "r"(b1));
}
__device__ __forceinline__ uint32_t pack_hl(float v) {
    __nv_bfloat16 h = __float2bfloat16(v);
    __nv_bfloat16 l = __float2bfloat16(v - __bfloat162float(h));
    return (uint32_t)__bfloat16_as_ushort(h) | ((uint32_t)__bfloat16_as_ushort(l) << 16);
}

// ---------------- scratch ----------------
__device__ uint32_t g_xP[BSZ * CCH * HWN];     // packed bf16 hi/lo of x2d
__device__ uint32_t g_hP[BSZ * CCH * HWN];     // packed off1 output (post-GELU)
__device__ float    g_mp[4 * MP_STRIDE];       // mod1 partials (pre-GELU)
__device__ float    g_op[4 * OP_STRIDE];       // off2 partials
__device__ float    g_mod[BSZ * 36 * HWN];     // mod2 out (post-sigmoid)

// prepacked bf16 hi/lo weights: [chunk = cb*9+tap][Npad][32]
#define W_TOTAL 502272
__device__ __nv_bfloat16 g_wHi[W_TOTAL];
__device__ __nv_bfloat16 g_wLo[W_TOTAL];

// ---------------- transpose + bf16-split-pack: [B,HW,C] -> packed [B,C,HW] ----------------
__global__ void transpose_kernel(const float* __restrict__ x, uint32_t* __restrict__ xP) {
    __shared__ float tile[32][33];
    int b  = blockIdx.z;
    int n0 = blockIdx.x * 32;
    int c0 = blockIdx.y * 32;
    int tx = threadIdx.x, ty = threadIdx.y;
    #pragma unroll
    for (int i = ty; i < 32; i += 8)
        tile[i][tx] = x[((size_t)b*HWN + n0 + i)*CCH + c0 + tx];
    __syncthreads();
    #pragma unroll
    for (int i = ty; i < 32; i += 8)
        xP[((size_t)b*CCH + c0 + i)*HWN + n0 + tx] = pack_hl(tile[tx][i]);
}

// ---------------- weight prepack ----------------
struct PackPart { const float* w; int dstBase, Cout, Npad, cinG, groups, elemsPerG; };

__global__ void prepack_kernel(PackPart p0, PackPart p1, PackPart p2, PackPart p3) {
    PackPart ps[4] = {p0, p1, p2, p3};
    long e = (long)blockIdx.x * 256 + threadIdx.x;
    int q = 0;
    for (; q < 4; q++) { long t = (long)ps[q].groups * ps[q].elemsPerG; if (e < t) break; e -= t; }
    if (q >= 4) return;
    PackPart pp = ps[q];
    int g  = (int)(e / pp.elemsPerG);
    int e2 = (int)(e - (long)g * pp.elemsPerG);
    int chunk = e2 / (pp.Npad * 32);
    int r     = e2 - chunk * (pp.Npad * 32);
    int n = r >> 5, j = r & 31;
    int cb = chunk / 9, tap = chunk - cb * 9;
    float v = 0.f;
    if (n < pp.Cout)
        v = pp.w[(((size_t)(g * pp.Cout + n)) * pp.cinG + cb * 32 + j) * 9 + tap];
    __nv_bfloat16 h = __float2bfloat16(v);
    long dst = pp.dstBase + (long)g * pp.elemsPerG + e2;
    g_wHi[dst] = h;
    g_wLo[dst] = __float2bfloat16(v - __bfloat162float(h));
}

// ---------------- implicit-GEMM conv via mma.sync ----------------
struct ConvPart {
    const void* in;              // packed u32, or fp32 partials base
    long inStride; int nPart;    // nPart fp32 partial buffers (if !inPacked)
    int inPacked, inAct;         // inAct: GELU after summing partials
    const __nv_bfloat16 *wHi, *wLo;
    const float* bias; void* out;
    int cinTotal, ciBase, coutTotal, coutBase, Cout, nCb, act, outPacked, addBias;
};
struct ConvArgs { ConvPart p[8]; };

#define SM_A_HI 0
#define SM_A_LO 21120
#define SM_B    42240
#define B_BUF   5760
#define SM_TOT  (42240 + 4*5760)   // 65280

template<int NFR>
__device__ __forceinline__ void stage_b(char* smem, const __nv_bfloat16* wHi,
                                        const __nv_bfloat16* wLo, int chunk, int par, int tid) {
    const int nv = NFR * 32;
    const uint4* sH = (const uint4*)(wHi + (size_t)chunk * (NFR * 8 * 32));
    const uint4* sL = (const uint4*)(wLo + (size_t)chunk * (NFR * 8 * 32));
    for (int i = tid; i < 2 * nv; i += 256) {
        int arr = (i >= nv);
        int ii  = arr ? i - nv : i;
        uint4 v = arr ? sL[ii] : sH[ii];
        int n = ii >> 2, qq = ii & 3;
        *(uint4*)(smem + SM_B + (size_t)(par * 2 + arr) * B_BUF + n * 80 + qq * 16) = v;
    }
}

template<int NFR>
__global__ void __launch_bounds__(256, 3) conv_mma(ConvArgs args) {
    extern __shared__ char smem[];
    const ConvPart P = args.p[blockIdx.y];
    const int tid = threadIdx.x;
    const int wid = tid >> 5, lid = tid & 31;
    const int b  = blockIdx.x >> 5;
    const int r0 = (blockIdx.x & 31) << 1;
    uint32_t sb = smem_u32(smem);

    float acc[NFR][4];
    #pragma unroll
    for (int i = 0; i < NFR; i++) { acc[i][0]=acc[i][1]=acc[i][2]=acc[i][3]=0.f; }

    const int m    = wid * 16 + (lid & 15);
    const int yloc = m >> 6, xpix = m & 63;
    const uint32_t aBase  = (uint32_t)(((yloc + 1) * 66 + (xpix + 1)) * 80) + ((lid >> 4) * 16);
    const int nloc4  = (lid & 7) + ((lid >> 4) << 3);
    const int khalfB = ((lid >> 3) & 1) * 16;

    #pragma unroll 1
    for (int cb = 0; cb < P.nCb; cb++) {
        __syncthreads();
        const size_t chBase = ((size_t)(b * P.cinTotal + P.ciBase + cb * 32)) * HWN;
        if (P.inPacked) {
            const uint32_t* ip = (const uint32_t*)P.in + chBase;
            #pragma unroll 1
            for (int i = tid; i < 4 * 66 * 32; i += 256) {
                int j   = i / 264;
                int pix = i - j * 264;
                int py = pix / 66, px = pix - py * 66;
                int y = r0 - 1 + py, x = px - 1;
                uint32_t w = 0;
                if ((unsigned)y < HH && (unsigned)x < WW) w = ip[(size_t)j * HWN + y * WW + x];
                uint32_t o = (uint32_t)(py * 66 + px) * 80 + j * 2;
                *(uint16_t*)(smem + SM_A_HI + o) = (uint16_t)w;
                *(uint16_t*)(smem + SM_A_LO + o) = (uint16_t)(w >> 16);
            }
        } else {
            const float* ip = (const float*)P.in + chBase;
            #pragma unroll 1
            for (int i = tid; i < 4 * 66 * 32; i += 256) {
                int j   = i / 264;
                int pix = i - j * 264;
                int py = pix / 66, px = pix - py * 66;
                int y = r0 - 1 + py, x = px - 1;
                float v = 0.f;
                if ((unsigned)y < HH && (unsigned)x < WW) {
                    size_t idx = (size_t)j * HWN + y * WW + x;
                    v = ip[idx];
                    for (int k = 1; k < P.nPart; k++) v += ip[idx + (size_t)k * P.inStride];
                    if (P.inAct) v = v * normcdff(v);
                }
                __nv_bfloat16 h = __float2bfloat16(v);
                __nv_bfloat16 l = __float2bfloat16(v - __bfloat162float(h));
                uint32_t o = (uint32_t)(py * 66 + px) * 80 + j * 2;
                *(__nv_bfloat16*)(smem + SM_A_HI + o) = h;
                *(__nv_bfloat16*)(smem + SM_A_LO + o) = l;
            }
        }
        stage_b<NFR>(smem, P.wHi, P.wLo, cb * 9, 0, tid);

        #pragma unroll 1
        for (int tap = 0; tap < 9; tap++) {
            __syncthreads();
            if (tap < 8) stage_b<NFR>(smem, P.wHi, P.wLo, cb * 9 + tap + 1, (tap + 1) & 1, tid);
            const int dy = tap / 3 - 1, dx = tap % 3 - 1;
            const uint32_t aOfs  = aBase + (dy * 66 + dx) * 80;
            const uint32_t bBase = sb + SM_B + (uint32_t)((tap & 1) * 2) * B_BUF;
            #pragma unroll
            for (int k16 = 0; k16 < 2; k16++) {
                uint32_t ah[4], al[4];
                ldsm_x4(ah, sb + SM_A_HI + aOfs + k16 * 32);
                ldsm_x4(al, sb + SM_A_LO + aOfs + k16 * 32);
                #pragma unroll
                for (int nf2 = 0; nf2 < NFR / 2; nf2++) {
                    uint32_t bAddr = bBase + (uint32_t)(nf2 * 16 + nloc4) * 80 + k16 * 32 + khalfB;
                    uint32_t bh[4], bl[4];
                    ldsm_x4(bh, bAddr);
                    ldsm_x4(bl, bAddr + B_BUF);
                    mma_bf16(acc[nf2*2],   ah, bh[0], bh[1]);
                    mma_bf16(acc[nf2*2+1], ah, bh[2], bh[3]);
                    mma_bf16(acc[nf2*2],   al, bh[0], bh[1]);
                    mma_bf16(acc[nf2*2+1], al, bh[2], bh[3]);
                    mma_bf16(acc[nf2*2],   ah, bl[0], bl[1]);
                    mma_bf16(acc[nf2*2+1], ah, bl[2], bl[3]);
                }
                if (NFR & 1) {
                    const int nf = NFR - 1;
                    uint32_t bAddr = bBase + (uint32_t)(nf * 8 + (lid & 7)) * 80 + k16 * 32 + khalfB;
                    uint32_t bh[2], bl[2];
                    ldsm_x2(bh, bAddr);
                    ldsm_x2(bl, bAddr + B_BUF);
                    mma_bf16(acc[nf], ah, bh[0], bh[1]);
                    mma_bf16(acc[nf], al, bh[0], bh[1]);
                    mma_bf16(acc[nf], ah, bl[0], bl[1]);
                }
            }
        }
    }

    // epilogue via smem transpose for coalesced stores
    __syncthreads();
    float* sd = (float*)smem;
    {
        const int rr = lid >> 2, cc = (lid & 3) * 2;
        const int mB = wid * 16;
        #pragma unroll
        for (int nf = 0; nf < NFR; nf++) {
            int n = nf * 8 + cc;
            sd[(n    ) * 132 + mB + rr    ] = acc[nf][0];
            sd[(n + 1) * 132 + mB + rr    ] = acc[nf][1];
            sd[(n    ) * 132 + mB + rr + 8] = acc[nf][2];
            sd[(n + 1) * 132 + mB + rr + 8] = acc[nf][3];
        }
    }
    __syncthreads();
    const int pixBase = r0 * WW;
    for (int i = tid; i < P.Cout * 128; i += 256) {
        int n = i >> 7, mm = i & 127;
        float v = sd[n * 132 + mm] + (P.addBias ? P.bias[n] : 0.f);
        if (P.act == 1)      v = v * normcdff(v);
        else if (P.act == 2) v = 1.f / (1.f + expf(-v));
        size_t oidx = ((size_t)(b * P.coutTotal + P.coutBase + n)) * HWN + pixBase + mm;
        if (P.outPacked) ((uint32_t*)P.out)[oidx] = pack_hl(v);
        else             ((float*)P.out)[oidx] = v;
    }
}

// ---------------- deformable sampling (sums 4 off partials) ----------------
__global__ void __launch_bounds__(256) sample_kernel(
    const float* __restrict__ x,     // [B, HW, C] native
    const float* __restrict__ op,    // 4 partials [B,72,HW], stride OP_STRIDE
    const float* __restrict__ mod,   // [B,36,HW]
    float* __restrict__ out)         // [B, HW, C]
{
    __shared__ float4 sw[36];
    __shared__ int4   so[36];

    const int t    = threadIdx.x;
    const int c    = t & 63;
    const int pl   = t >> 6;
    const int pix0 = blockIdx.x * 4;
    const int g    = blockIdx.y;
    const int b    = blockIdx.z;

    if (t < 36) {
        const int pli = t / 9;
        const int p   = t - pli * 9;
        const int pix = pix0 + pli;
        const int yq  = pix >> 6;
        const int xq  = pix & 63;

        const float* offp = op  + ((size_t)b*72 + g*18)*HWN + pix;
        const float* modp = mod + ((size_t)b*36 + g*9 )*HWN + pix;

        float ox = 0.f, oy = 0.f;
        #pragma unroll
        for (int k = 0; k < 4; k++) {
            ox += offp[(size_t)k*OP_STRIDE + (size_t)p*HWN];
            oy += offp[(size_t)k*OP_STRIDE + (size_t)(9+p)*HWN];
        }
        float mv = modp[(size_t)p*HWN] * (1.f/9.f);

        float px = fminf(fmaxf((float)(xq + (p%3) - 1) + ox, 0.f), (float)(WW-1));
        float py = fminf(fmaxf((float)(yq + (p/3) - 1) + oy, 0.f), (float)(HH-1));

        float x0f = floorf(px), y0f = floorf(py);
        float wx = px - x0f, wy = py - y0f;
        int x0 = (int)x0f, y0 = (int)y0f;
        int x1 = min(x0 + 1, WW-1);
        int y1 = min(y0 + 1, HH-1);

        sw[t] = make_float4((1.f-wx)*(1.f-wy)*mv, wx*(1.f-wy)*mv,
                            (1.f-wx)*wy*mv,       wx*wy*mv);
        so[t] = make_int4((y0*WW + x0)*CCH, (y0*WW + x1)*CCH,
                          (y1*WW + x0)*CCH, (y1*WW + x1)*CCH);
    }
    __syncthreads();

    const float* xb = x + (size_t)b*HWN*CCH + g*CG + c;
    float acc = 0.f;
    #pragma unroll
    for (int p = 0; p < 9; p++) {
        float4 w = sw[pl*9 + p];
        int4   o = so[pl*9 + p];
        float v00 = __ldg(xb + o.x);
        float v01 = __ldg(xb + o.y);
        float v10 = __ldg(xb + o.z);
        float v11 = __ldg(xb + o.w);
        acc += v00*w.x + v01*w.y + v10*w.z + v11*w.w;
    }
    out[((size_t)b*HWN + pix0 + pl)*CCH + g*CG + c] = acc;
}

// ---------------- launch ----------------
extern "C" void kernel_launch(void* const* d_in, const int* in_sizes, int n_in,
                              void* d_out, int out_size)
{
    const float* x      = (const float*)d_in[0];
    const float* off_w1 = (const float*)d_in[1];
    const float* off_b1 = (const float*)d_in[2];
    const float* off_w2 = (const float*)d_in[3];
    const float* off_b2 = (const float*)d_in[4];
    const float* mod_w1 = (const float*)d_in[5];
    const float* mod_b1 = (const float*)d_in[6];
    const float* mod_w2 = (const float*)d_in[7];
    const float* mod_b2 = (const float*)d_in[8];
    float* out = (float*)d_out;

    uint32_t *xP, *hP;
    float *mp, *op, *md;
    cudaGetSymbolAddress((void**)&xP, g_xP);
    cudaGetSymbolAddress((void**)&hP, g_hP);
    cudaGetSymbolAddress((void**)&mp, g_mp);
    cudaGetSymbolAddress((void**)&op, g_op);
    cudaGetSymbolAddress((void**)&md, g_mod);

    __nv_bfloat16 *wHi, *wLo;
    cudaGetSymbolAddress((void**)&wHi, g_wHi);
    cudaGetSymbolAddress((void**)&wLo, g_wLo);

    cudaFuncSetAttribute(conv_mma<8>, cudaFuncAttributeMaxDynamicSharedMemorySize, SM_TOT);
    cudaFuncSetAttribute(conv_mma<9>, cudaFuncAttributeMaxDynamicSharedMemorySize, SM_TOT);

    // 1) transpose + pack
    {
        dim3 grid(HWN/32, CCH/32, BSZ), blk(32, 8);
        transpose_kernel<<<grid, blk>>>(x, xP);
    }
    // 2) weight prepack
    {
        PackPart p0; p0.w = off_w1; p0.dstBase = 0;      p0.Cout = 64; p0.Npad = 64; p0.cinG = 64;  p0.groups = 4; p0.elemsPerG = 2*9*64*32;
        PackPart p1; p1.w = mod_w1; p1.dstBase = 147456; p1.Cout = 64; p1.Npad = 64; p1.cinG = 256; p1.groups = 1; p1.elemsPerG = 8*9*64*32;
        PackPart p2; p2.w = off_w2; p2.dstBase = 294912; p2.Cout = 72; p2.Npad = 72; p2.cinG = 256; p2.groups = 1; p2.elemsPerG = 8*9*72*32;
        PackPart p3; p3.w = mod_w2; p3.dstBase = 460800; p3.Cout = 36; p3.Npad = 72; p3.cinG = 64;  p3.groups = 1; p3.elemsPerG = 2*9*72*32;
        long total = 4L*36864 + 147456 + 165888 + 41472;
        prepack_kernel<<<(int)((total + 255)/256), 256>>>(p0, p1, p2, p3);
    }
    // 3) stage 1 (NFR=8): 4 mod1 cin-chunks (partials) + 4 off1 groups (packed out) — all nCb=2
    {
        ConvArgs a;
        for (int k = 0; k < 4; k++) {
            ConvPart& P = a.p[k];
            P.in = xP; P.inStride = 0; P.nPart = 1; P.inPacked = 1; P.inAct = 0;
            P.wHi = wHi + 147456 + (size_t)k*36864; P.wLo = wLo + 147456 + (size_t)k*36864;
            P.bias = mod_b1; P.out = mp + (size_t)k*MP_STRIDE;
            P.cinTotal = 256; P.ciBase = k*64; P.coutTotal = 64; P.coutBase = 0;
            P.Cout = 64; P.nCb = 2; P.act = 0; P.outPacked = 0; P.addBias = (k == 0);
        }
        for (int g = 0; g < 4; g++) {
            ConvPart& P = a.p[4 + g];
            P.in = xP; P.inStride = 0; P.nPart = 1; P.inPacked = 1; P.inAct = 0;
            P.wHi = wHi + (size_t)g*36864; P.wLo = wLo + (size_t)g*36864;
            P.bias = off_b1 + g*64; P.out = hP;
            P.cinTotal = 256; P.ciBase = g*64; P.coutTotal = 256; P.coutBase = g*64;
            P.Cout = 64; P.nCb = 2; P.act = 1; P.outPacked = 1; P.addBias = 1;
        }
        conv_mma<8><<<dim3(128, 8), 256, SM_TOT>>>(a);
    }
    // 4) stage 2 (NFR=9): 4 off2 cin-chunks (partials) + mod2 (sums 4 mod1 partials, GELU on load)
    {
        ConvArgs a;
        for (int k = 0; k < 4; k++) {
            ConvPart& P = a.p[k];
            P.in = hP; P.inStride = 0; P.nPart = 1; P.inPacked = 1; P.inAct = 0;
            P.wHi = wHi + 294912 + (size_t)k*41472; P.wLo = wLo + 294912 + (size_t)k*41472;
            P.bias = off_b2; P.out = op + (size_t)k*OP_STRIDE;
            P.cinTotal = 256; P.ciBase = k*64; P.coutTotal = 72; P.coutBase = 0;
            P.Cout = 72; P.nCb = 2; P.act = 0; P.outPacked = 0; P.addBias = (k == 0);
        }
        ConvPart& Q = a.p[4];
        Q.in = mp; Q.inStride = MP_STRIDE; Q.nPart = 4; Q.inPacked = 0; Q.inAct = 1;
        Q.wHi = wHi + 460800; Q.wLo = wLo + 460800;
        Q.bias = mod_b2; Q.out = md;
        Q.cinTotal = 64; Q.ciBase = 0; Q.coutTotal = 36; Q.coutBase = 0;
        Q.Cout = 36; Q.nCb = 2; Q.act = 2; Q.outPacked = 0; Q.addBias = 1;
        for (int k = 5; k < 8; k++) a.p[k] = a.p[4];  // unused
        conv_mma<9><<<dim3(128, 5), 256, SM_TOT>>>(a);
    }
    // 5) sampling
    {
        dim3 grid(HWN/4, GG, BSZ);
        sample_kernel<<<grid, 256>>>(x, op, md, out);
    }
}

// round 8
// speedup vs baseline: 2.1746x; 1.0237x over previous
#include <cuda_runtime.h>
#include <cuda_bf16.h>
#include <cstdint>

#define BSZ 4
#define CCH 256
#define HH 64
#define WW 64
#define HWN 4096
#define GG 4
#define CG 64

#define MP_STRIDE (BSZ*64*HWN)    // per mod1-partial buffer (floats)
#define OP_STRIDE (BSZ*72*HWN)    // per off2-partial buffer (floats)

// ---------------- warp-MMA helpers ----------------
__device__ __forceinline__ uint32_t smem_u32(const void* p){
  uint32_t a; asm("{ .reg .u64 t; cvta.to.shared.u64 t, %1; cvt.u32.u64 %0, t; }" : "=r"(a) : "l"(p)); return a;
}
__device__ __forceinline__ void ldsm_x4(uint32_t* r, uint32_t a) {
    asm volatile("ldmatrix.sync.aligned.m8n8.x4.shared.b16 {%0,%1,%2,%3}, [%4];"
        : "=r"(r[0]), "=r"(r[1]), "=r"(r[2]), "=r"(r[3]) : "r"(a));
}
__device__ __forceinline__ void ldsm_x2(uint32_t* r, uint32_t a) {
    asm volatile("ldmatrix.sync.aligned.m8n8.x2.shared.b16 {%0,%1}, [%2];"
        : "=r"(r[0]), "=r"(r[1]) : "r"(a));
}
__device__ __forceinline__ void mma_bf16(float* d, const uint32_t* a, uint32_t b0, uint32_t b1) {
    asm volatile("mma.sync.aligned.m16n8k16.row.col.f32.bf16.bf16.f32 "
        "{%0,%1,%2,%3}, {%4,%5,%6,%7}, {%8,%9}, {%0,%1,%2,%3};"
        : "+f"(d[0]), "+f"(d[1]), "+f"(d[2]), "+f"(d[3])
        : "r"(a[0]), "r"(a[1]), "r"(a[2]), "r"(a[3]), "r"(b0), "r"(b1));
}
__device__ __forceinline__ uint32_t pack_hl(float v) {
    __nv_bfloat16 h = __float2bfloat16(v);
    __nv_bfloat16 l = __float2bfloat16(v - __bfloat162float(h));
    return (uint32_t)__bfloat16_as_ushort(h) | ((uint32_t)__bfloat16_as_ushort(l) << 16);
}

// ---------------- scratch ----------------
__device__ uint32_t g_xP[BSZ * CCH * HWN];     // packed bf16 hi/lo of x2d
__device__ uint32_t g_hP[BSZ * CCH * HWN];     // packed off1 output (post-GELU)
__device__ float    g_mp[4 * MP_STRIDE];       // mod1 partials (pre-GELU)
__device__ float    g_op[4 * OP_STRIDE];       // off2 partials
__device__ float    g_mod[BSZ * 36 * HWN];     // mod2 out (post-sigmoid)

// prepacked bf16 hi/lo weights; per part: [chunk=cb*9+tap][rowsPad][32]
#define W_TOTAL 502272
__device__ __nv_bfloat16 g_wHi[W_TOTAL];
__device__ __nv_bfloat16 g_wLo[W_TOTAL];

// ---------------- transpose + bf16-split-pack ----------------
__global__ void transpose_kernel(const float* __restrict__ x, uint32_t* __restrict__ xP) {
    __shared__ float tile[32][33];
    int b  = blockIdx.z;
    int n0 = blockIdx.x * 32;
    int c0 = blockIdx.y * 32;
    int tx = threadIdx.x, ty = threadIdx.y;
    #pragma unroll
    for (int i = ty; i < 32; i += 8)
        tile[i][tx] = x[((size_t)b*HWN + n0 + i)*CCH + c0 + tx];
    __syncthreads();
    #pragma unroll
    for (int i = ty; i < 32; i += 8)
        xP[((size_t)b*CCH + c0 + i)*HWN + n0 + tx] = pack_hl(tile[tx][i]);
}

// ---------------- weight prepack (25 parts) ----------------
struct PackPart { const float* w; int dstBase, wCinG, nInW0, ciInW0, CoutValid, rowsPad; };
struct PackAll  { PackPart p[25]; };

__global__ void prepack_kernel(PackAll a) {
    long e = (long)blockIdx.x * 256 + threadIdx.x;
    int q = 0;
    for (; q < 25; q++) {
        long t = 18L * a.p[q].rowsPad * 32;
        if (e < t) break;
        e -= t;
    }
    if (q >= 25) return;
    PackPart pp = a.p[q];
    int e2 = (int)e;
    int chunk = e2 / (pp.rowsPad * 32);
    int r     = e2 - chunk * (pp.rowsPad * 32);
    int row = r >> 5, j = r & 31;
    int cb = chunk / 9, tap = chunk - cb * 9;
    float v = 0.f;
    if (row < pp.CoutValid)
        v = pp.w[(((size_t)(pp.nInW0 + row)) * pp.wCinG + pp.ciInW0 + cb * 32 + j) * 9 + tap];
    __nv_bfloat16 h = __float2bfloat16(v);
    long dst = pp.dstBase + e;
    g_wHi[dst] = h;
    g_wLo[dst] = __float2bfloat16(v - __bfloat162float(h));
}

// ---------------- implicit-GEMM conv via mma.sync ----------------
struct ConvPart {
    const void* in;
    long inStride; int nPart;
    int inPacked, inAct;
    const __nv_bfloat16 *wHi, *wLo;       // pre-offset to part base
    const float* bias;                     // pre-offset to coutBase
    void* out;
    int cinTotal, ciBase, coutTotal, coutBase, CoutValid, nCb, act, outPacked, addBias;
};
struct ConvArgs { ConvPart p[16]; };

#define SM_A_HI 0
#define SM_A_LO 21120
#define SM_B    42240

template<int NFR>
__device__ __forceinline__ void stage_b(char* smem, const __nv_bfloat16* wHi,
                                        const __nv_bfloat16* wLo, int chunk, int par, int tid) {
    constexpr int BBUF = NFR * 8 * 80;
    const int nv = NFR * 32;
    const uint4* sH = (const uint4*)(wHi + (size_t)chunk * (NFR * 8 * 32));
    const uint4* sL = (const uint4*)(wLo + (size_t)chunk * (NFR * 8 * 32));
    for (int i = tid; i < 2 * nv; i += 256) {
        int arr = (i >= nv);
        int ii  = arr ? i - nv : i;
        uint4 v = arr ? sL[ii] : sH[ii];
        int n = ii >> 2, qq = ii & 3;
        *(uint4*)(smem + SM_B + (size_t)(par * 2 + arr) * BBUF + n * 80 + qq * 16) = v;
    }
}

template<int NFR>
__global__ void __launch_bounds__(256, 4) conv_mma(ConvArgs args) {
    constexpr int BBUF = NFR * 8 * 80;
    extern __shared__ char smem[];
    const ConvPart P = args.p[blockIdx.y];
    const int tid = threadIdx.x;
    const int wid = tid >> 5, lid = tid & 31;
    const int b  = blockIdx.x >> 5;
    const int r0 = (blockIdx.x & 31) << 1;
    uint32_t sb = smem_u32(smem);

    float acc[NFR][4];
    #pragma unroll
    for (int i = 0; i < NFR; i++) { acc[i][0]=acc[i][1]=acc[i][2]=acc[i][3]=0.f; }

    const int m    = wid * 16 + (lid & 15);
    const int yloc = m >> 6, xpix = m & 63;
    const uint32_t aBase  = (uint32_t)(((yloc + 1) * 66 + (xpix + 1)) * 80) + ((lid >> 4) * 16);
    const int nloc4  = (lid & 7) + ((lid >> 4) << 3);
    const int khalfB = ((lid >> 3) & 1) * 16;

    #pragma unroll 1
    for (int cb = 0; cb < P.nCb; cb++) {
        __syncthreads();
        const size_t chBase = ((size_t)(b * P.cinTotal + P.ciBase + cb * 32)) * HWN;
        if (P.inPacked) {
            const uint32_t* ip = (const uint32_t*)P.in + chBase;
            #pragma unroll 1
            for (int i = tid; i < 4 * 66 * 32; i += 256) {
                int j   = i / 264;
                int pix = i - j * 264;
                int py = pix / 66, px = pix - py * 66;
                int y = r0 - 1 + py, x = px - 1;
                uint32_t w = 0;
                if ((unsigned)y < HH && (unsigned)x < WW) w = ip[(size_t)j * HWN + y * WW + x];
                uint32_t o = (uint32_t)(py * 66 + px) * 80 + j * 2;
                *(uint16_t*)(smem + SM_A_HI + o) = (uint16_t)w;
                *(uint16_t*)(smem + SM_A_LO + o) = (uint16_t)(w >> 16);
            }
        } else {
            const float* ip = (const float*)P.in + chBase;
            #pragma unroll 1
            for (int i = tid; i < 4 * 66 * 32; i += 256) {
                int j   = i / 264;
                int pix = i - j * 264;
                int py = pix / 66, px = pix - py * 66;
                int y = r0 - 1 + py, x = px - 1;
                float v = 0.f;
                if ((unsigned)y < HH && (unsigned)x < WW) {
                    size_t idx = (size_t)j * HWN + y * WW + x;
                    v = ip[idx];
                    for (int k = 1; k < P.nPart; k++) v += ip[idx + (size_t)k * P.inStride];
                    if (P.inAct) v = v * normcdff(v);
                }
                __nv_bfloat16 h = __float2bfloat16(v);
                __nv_bfloat16 l = __float2bfloat16(v - __bfloat162float(h));
                uint32_t o = (uint32_t)(py * 66 + px) * 80 + j * 2;
                *(__nv_bfloat16*)(smem + SM_A_HI + o) = h;
                *(__nv_bfloat16*)(smem + SM_A_LO + o) = l;
            }
        }
        stage_b<NFR>(smem, P.wHi, P.wLo, cb * 9, 0, tid);

        #pragma unroll 1
        for (int tap = 0; tap < 9; tap++) {
            __syncthreads();
            if (tap < 8) stage_b<NFR>(smem, P.wHi, P.wLo, cb * 9 + tap + 1, (tap + 1) & 1, tid);
            const int dy = tap / 3 - 1, dx = tap % 3 - 1;
            const uint32_t aOfs  = aBase + (dy * 66 + dx) * 80;
            const uint32_t bBase = sb + SM_B + (uint32_t)((tap & 1) * 2) * BBUF;
            #pragma unroll
            for (int k16 = 0; k16 < 2; k16++) {
                uint32_t ah[4], al[4];
                ldsm_x4(ah, sb + SM_A_HI + aOfs + k16 * 32);
                ldsm_x4(al, sb + SM_A_LO + aOfs + k16 * 32);
                #pragma unroll
                for (int nf2 = 0; nf2 < NFR / 2; nf2++) {
                    uint32_t bAddr = bBase + (uint32_t)(nf2 * 16 + nloc4) * 80 + k16 * 32 + khalfB;
                    uint32_t bh[4], bl[4];
                    ldsm_x4(bh, bAddr);
                    ldsm_x4(bl, bAddr + BBUF);
                    mma_bf16(acc[nf2*2],   ah, bh[0], bh[1]);
                    mma_bf16(acc[nf2*2+1], ah, bh[2], bh[3]);
                    mma_bf16(acc[nf2*2],   al, bh[0], bh[1]);
                    mma_bf16(acc[nf2*2+1], al, bh[2], bh[3]);
                    mma_bf16(acc[nf2*2],   ah, bl[0], bl[1]);
                    mma_bf16(acc[nf2*2+1], ah, bl[2], bl[3]);
                }
                if (NFR & 1) {
                    const int nf = NFR - 1;
                    uint32_t bAddr = bBase + (uint32_t)(nf * 8 + (lid & 7)) * 80 + k16 * 32 + khalfB;
                    uint32_t bh[2], bl[2];
                    ldsm_x2(bh, bAddr);
                    ldsm_x2(bl, bAddr + BBUF);
                    mma_bf16(acc[nf], ah, bh[0], bh[1]);
                    mma_bf16(acc[nf], al, bh[0], bh[1]);
                    mma_bf16(acc[nf], ah, bl[0], bl[1]);
                }
            }
        }
    }

    // epilogue via smem transpose for coalesced stores
    __syncthreads();
    float* sd = (float*)smem;
    {
        const int rr = lid >> 2, cc = (lid & 3) * 2;
        const int mB = wid * 16;
        #pragma unroll
        for (int nf = 0; nf < NFR; nf++) {
            int n = nf * 8 + cc;
            sd[(n    ) * 132 + mB + rr    ] = acc[nf][0];
            sd[(n + 1) * 132 + mB + rr    ] = acc[nf][1];
            sd[(n    ) * 132 + mB + rr + 8] = acc[nf][2];
            sd[(n + 1) * 132 + mB + rr + 8] = acc[nf][3];
        }
    }
    __syncthreads();
    const int pixBase = r0 * WW;
    for (int i = tid; i < P.CoutValid * 128; i += 256) {
        int n = i >> 7, mm = i & 127;
        float v = sd[n * 132 + mm] + (P.addBias ? P.bias[n] : 0.f);
        if (P.act == 1)      v = v * normcdff(v);
        else if (P.act == 2) v = 1.f / (1.f + expf(-v));
        size_t oidx = ((size_t)(b * P.coutTotal + P.coutBase + n)) * HWN + pixBase + mm;
        if (P.outPacked) ((uint32_t*)P.out)[oidx] = pack_hl(v);
        else             ((float*)P.out)[oidx] = v;
    }
}

// ---------------- deformable sampling (sums 4 off partials) ----------------
__global__ void __launch_bounds__(256) sample_kernel(
    const float* __restrict__ x,
    const float* __restrict__ op,
    const float* __restrict__ mod,
    float* __restrict__ out)
{
    __shared__ float4 sw[36];
    __shared__ int4   so[36];

    const int t    = threadIdx.x;
    const int c    = t & 63;
    const int pl   = t >> 6;
    const int pix0 = blockIdx.x * 4;
    const int g    = blockIdx.y;
    const int b    = blockIdx.z;

    if (t < 36) {
        const int pli = t / 9;
        const int p   = t - pli * 9;
        const int pix = pix0 + pli;
        const int yq  = pix >> 6;
        const int xq  = pix & 63;

        const float* offp = op  + ((size_t)b*72 + g*18)*HWN + pix;
        const float* modp = mod + ((size_t)b*36 + g*9 )*HWN + pix;

        float ox = 0.f, oy = 0.f;
        #pragma unroll
        for (int k = 0; k < 4; k++) {
            ox += offp[(size_t)k*OP_STRIDE + (size_t)p*HWN];
            oy += offp[(size_t)k*OP_STRIDE + (size_t)(9+p)*HWN];
        }
        float mv = modp[(size_t)p*HWN] * (1.f/9.f);

        float px = fminf(fmaxf((float)(xq + (p%3) - 1) + ox, 0.f), (float)(WW-1));
        float py = fminf(fmaxf((float)(yq + (p/3) - 1) + oy, 0.f), (float)(HH-1));

        float x0f = floorf(px), y0f = floorf(py);
        float wx = px - x0f, wy = py - y0f;
        int x0 = (int)x0f, y0 = (int)y0f;
        int x1 = min(x0 + 1, WW-1);
        int y1 = min(y0 + 1, HH-1);

        sw[t] = make_float4((1.f-wx)*(1.f-wy)*mv, wx*(1.f-wy)*mv,
                            (1.f-wx)*wy*mv,       wx*wy*mv);
        so[t] = make_int4((y0*WW + x0)*CCH, (y0*WW + x1)*CCH,
                          (y1*WW + x0)*CCH, (y1*WW + x1)*CCH);
    }
    __syncthreads();

    const float* xb = x + (size_t)b*HWN*CCH + g*CG + c;
    float acc = 0.f;
    #pragma unroll
    for (int p = 0; p < 9; p++) {
        float4 w = sw[pl*9 + p];
        int4   o = so[pl*9 + p];
        float v00 = __ldg(xb + o.x);
        float v01 = __ldg(xb + o.y);
        float v10 = __ldg(xb + o.z);
        float v11 = __ldg(xb + o.w);
        acc += v00*w.x + v01*w.y + v10*w.z + v11*w.w;
    }
    out[((size_t)b*HWN + pix0 + pl)*CCH + g*CG + c] = acc;
}

// ---------------- launch ----------------
extern "C" void kernel_launch(void* const* d_in, const int* in_sizes, int n_in,
                              void* d_out, int out_size)
{
    const float* x      = (const float*)d_in[0];
    const float* off_w1 = (const float*)d_in[1];
    const float* off_b1 = (const float*)d_in[2];
    const float* off_w2 = (const float*)d_in[3];
    const float* off_b2 = (const float*)d_in[4];
    const float* mod_w1 = (const float*)d_in[5];
    const float* mod_b1 = (const float*)d_in[6];
    const float* mod_w2 = (const float*)d_in[7];
    const float* mod_b2 = (const float*)d_in[8];
    float* out = (float*)d_out;

    uint32_t *xP, *hP;
    float *mp, *op, *md;
    cudaGetSymbolAddress((void**)&xP, g_xP);
    cudaGetSymbolAddress((void**)&hP, g_hP);
    cudaGetSymbolAddress((void**)&mp, g_mp);
    cudaGetSymbolAddress((void**)&op, g_op);
    cudaGetSymbolAddress((void**)&md, g_mod);

    __nv_bfloat16 *wHi, *wLo;
    cudaGetSymbolAddress((void**)&wHi, g_wHi);
    cudaGetSymbolAddress((void**)&wLo, g_wLo);

    const int SMT4 = 42240 + 4 * (4 * 8 * 80);   // 52480
    const int SMT5 = 42240 + 4 * (5 * 8 * 80);   // 55040
    cudaFuncSetAttribute(conv_mma<4>, cudaFuncAttributeMaxDynamicSharedMemorySize, SMT4);
    cudaFuncSetAttribute(conv_mma<5>, cudaFuncAttributeMaxDynamicSharedMemorySize, SMT5);

    // 1) transpose + pack
    {
        dim3 grid(HWN/32, CCH/32, BSZ), blk(32, 8);
        transpose_kernel<<<grid, blk>>>(x, xP);
    }
    // 2) weight prepack: 25 parts
    // stage1 (rowsPad 32): mod1 k=0..3 x nh=0..1 (8), off1 g=0..3 x nh=0..1 (8)
    // stage2 (rowsPad 40): off2 k=0..3 x nh=0..1 (8), mod2 (1)
    int s1Base[16], s2Base[9];
    {
        PackAll pa;
        int idx = 0, dst = 0;
        for (int k = 0; k < 4; k++)
            for (int nh = 0; nh < 2; nh++) {
                pa.p[idx] = { mod_w1, dst, 256, nh*32, k*64, 32, 32 };
                s1Base[idx] = dst; idx++; dst += 18*32*32;
            }
        for (int g = 0; g < 4; g++)
            for (int nh = 0; nh < 2; nh++) {
                pa.p[idx] = { off_w1, dst, 64, g*64 + nh*32, 0, 32, 32 };
                s1Base[idx] = dst; idx++; dst += 18*32*32;
            }
        int idx2 = 0;
        for (int k = 0; k < 4; k++)
            for (int nh = 0; nh < 2; nh++) {
                pa.p[idx] = { off_w2, dst, 256, nh*40, k*64, nh ? 32 : 40, 40 };
                s2Base[idx2] = dst; idx++; idx2++; dst += 18*40*32;
            }
        pa.p[idx] = { mod_w2, dst, 64, 0, 0, 36, 40 };
        s2Base[idx2] = dst;
        long total = (long)dst + 18*40*32;       // 502272
        prepack_kernel<<<(int)((total + 255)/256), 256>>>(pa);
    }
    // 3) stage 1 (NFR=4, 16 parts): mod1 partials (cin-split x4, n-split x2) + off1 (4 groups x n-split x2)
    {
        ConvArgs a;
        int idx = 0;
        for (int k = 0; k < 4; k++)
            for (int nh = 0; nh < 2; nh++) {
                ConvPart& P = a.p[idx];
                P.in = xP; P.inStride = 0; P.nPart = 1; P.inPacked = 1; P.inAct = 0;
                P.wHi = wHi + s1Base[idx]; P.wLo = wLo + s1Base[idx];
                P.bias = mod_b1 + nh*32; P.out = mp + (size_t)k*MP_STRIDE;
                P.cinTotal = 256; P.ciBase = k*64; P.coutTotal = 64; P.coutBase = nh*32;
                P.CoutValid = 32; P.nCb = 2; P.act = 0; P.outPacked = 0; P.addBias = (k == 0);
                idx++;
            }
        for (int g = 0; g < 4; g++)
            for (int nh = 0; nh < 2; nh++) {
                ConvPart& P = a.p[idx];
                P.in = xP; P.inStride = 0; P.nPart = 1; P.inPacked = 1; P.inAct = 0;
                P.wHi = wHi + s1Base[idx]; P.wLo = wLo + s1Base[idx];
                P.bias = off_b1 + g*64 + nh*32; P.out = hP;
                P.cinTotal = 256; P.ciBase = g*64; P.coutTotal = 256; P.coutBase = g*64 + nh*32;
                P.CoutValid = 32; P.nCb = 2; P.act = 1; P.outPacked = 1; P.addBias = 1;
                idx++;
            }
        conv_mma<4><<<dim3(128, 16), 256, SMT4>>>(a);
    }
    // 4) stage 2 (NFR=5, 9 parts): off2 partials (cin x4, n-split 40/32) + mod2
    {
        ConvArgs a;
        int idx = 0;
        for (int k = 0; k < 4; k++)
            for (int nh = 0; nh < 2; nh++) {
                ConvPart& P = a.p[idx];
                P.in = hP; P.inStride = 0; P.nPart = 1; P.inPacked = 1; P.inAct = 0;
                P.wHi = wHi + s2Base[idx]; P.wLo = wLo + s2Base[idx];
                P.bias = off_b2 + nh*40; P.out = op + (size_t)k*OP_STRIDE;
                P.cinTotal = 256; P.ciBase = k*64; P.coutTotal = 72; P.coutBase = nh*40;
                P.CoutValid = nh ? 32 : 40; P.nCb = 2; P.act = 0; P.outPacked = 0; P.addBias = (k == 0);
                idx++;
            }
        ConvPart& Q = a.p[idx];
        Q.in = mp; Q.inStride = MP_STRIDE; Q.nPart = 4; Q.inPacked = 0; Q.inAct = 1;
        Q.wHi = wHi + s2Base[idx]; Q.wLo = wLo + s2Base[idx];
        Q.bias = mod_b2; Q.out = md;
        Q.cinTotal = 64; Q.ciBase = 0; Q.coutTotal = 36; Q.coutBase = 0;
        Q.CoutValid = 36; Q.nCb = 2; Q.act = 2; Q.outPacked = 0; Q.addBias = 1;
        conv_mma<5><<<dim3(128, 9), 256, SMT5>>>(a);
    }
    // 5) sampling
    {
        dim3 grid(HWN/4, GG, BSZ);
        sample_kernel<<<grid, 256>>>(x, op, md, out);
    }
}